// round 7
// baseline (speedup 1.0000x reference)
#include <cuda_runtime.h>
#include <cuda_fp16.h>
#include <math.h>
#include <stdint.h>

// Problem constants
#define Hdim 512
#define Lsteps 16
#define Nrows 8192
#define NH (Nrows * Hdim)

// ---------------- scratch (device globals) ------------------------------------
__device__ __half g_P[Lsteps * (size_t)NH];  // precomputed el@W2 + xl@W4 (fp16)
__device__ __half g_C0[NH];                  // x0@W3 + b_xi (fp16)
__device__ __half g_U[NH];                   // u gate (fp16)
// fp16 activations / inputs
__device__ __half g_E16[Lsteps * (size_t)NH];
__device__ __half g_N16[(Lsteps + 1) * (size_t)NH];
__device__ __half g_X0H16[NH];
__device__ __half g_XTH16[NH];
__device__ __half g_RH16[NH];
__device__ __half g_HX16[NH];
// fp16 transposed weights [n][k]
__device__ __half g_W1T[512 * 512];
__device__ __half g_WpT[512 * 1024];
__device__ __half g_W3T[512 * 512];
__device__ __half g_WurT[1024 * 1536];
__device__ __half g_WkT[512 * 1536];

// ---------------- helpers -------------------------------------------------------
__device__ __forceinline__ uint32_t smem_u32(const void* p) {
    uint32_t a;
    asm("{ .reg .u64 t; cvta.to.shared.u64 t, %1; cvt.u32.u64 %0, t; }" : "=r"(a) : "l"(p));
    return a;
}
__device__ __forceinline__ void cp_async16(void* dst, const void* src) {
    asm volatile("cp.async.cg.shared.global [%0], [%1], 16;"
                 :: "r"(smem_u32(dst)), "l"(src) : "memory");
}
#define CP_COMMIT() asm volatile("cp.async.commit_group;" ::: "memory")
#define CP_WAIT1()  asm volatile("cp.async.wait_group 1;" ::: "memory")

__device__ __forceinline__ void ldsm_x4(uint32_t (&r)[4], uint32_t addr) {
    asm volatile("ldmatrix.sync.aligned.m8n8.x4.shared.b16 {%0,%1,%2,%3}, [%4];"
                 : "=r"(r[0]), "=r"(r[1]), "=r"(r[2]), "=r"(r[3]) : "r"(addr));
}
__device__ __forceinline__ void mma_f16(float (&d)[4], const uint32_t (&a)[4],
                                        uint32_t b0, uint32_t b1) {
    asm volatile(
        "mma.sync.aligned.m16n8k16.row.col.f32.f16.f16.f32 "
        "{%0,%1,%2,%3}, {%4,%5,%6,%7}, {%8,%9}, {%0,%1,%2,%3};"
        : "+f"(d[0]), "+f"(d[1]), "+f"(d[2]), "+f"(d[3])
        : "r"(a[0]), "r"(a[1]), "r"(a[2]), "r"(a[3]), "r"(b0), "r"(b1));
}
__device__ __forceinline__ float sigmoidf_(float x) { return 1.0f / (1.0f + expf(-x)); }

// ---------------- GEMM config ---------------------------------------------------
// CTA 256x128x64 fp16, 16 warps (warp tile 64x32), 3-stage cp.async pipeline.
#define AROW_B 144                      // 64 fp16 (128B) + 16B pad
#define A_ROWS 256
#define B_ROWS 128
#define STAGE_ROWS (A_ROWS + B_ROWS)    // 384
#define STAGE_B (STAGE_ROWS * AROW_B)   // 55296 B
#define NSTAGE 3
#define SMEM_BYTES (NSTAGE * STAGE_B)   // 165888

struct GemmArgs {
    const __half* A[3];         // K blocks of 512 (row-major fp16, ld = 512)
    const __half* Bt;           // transposed fp16 weights [Ntot][Ktot]
    int ldB;
    const __half* P;
    const __half* C0;
    const __half* x0;
    const __half* xl;
    const float* bias0;
    const float* bias1;
    const float* hx;
    const __half* U;
    float* out0;
    __half* out16a;
    __half* out16b;
};

#define MODE_PRE 0
#define MODE_C0  1
#define MODE_XI  2
#define MODE_UR  3
#define MODE_K   4

__device__ __forceinline__ float2 h2f(const __half* p) {
    return __half22float2(*(const __half2*)p);
}

template <int MODE>
__device__ __forceinline__ void epi(const GemmArgs& g, int row, int col, float v0, float v1) {
    int c512 = col & 511;
    size_t idx = (size_t)row * Hdim + c512;
    if (MODE == MODE_PRE) {
        *(__half2*)(g.out16a + idx) = __floats2half2_rn(v0, v1);
    } else if (MODE == MODE_C0) {
        float2 b = *(const float2*)(g.bias0 + c512);
        *(__half2*)(g.out16a + idx) = __floats2half2_rn(v0 + b.x, v1 + b.y);
    } else if (MODE == MODE_XI) {
        float2 p   = h2f(g.P  + idx);
        float2 c0v = h2f(g.C0 + idx);
        float2 x0v = h2f(g.x0 + idx);
        float2 xlv = h2f(g.xl + idx);
        float s0 = sigmoidf_(v0 + p.x + c0v.x);
        float s1 = sigmoidf_(v1 + p.y + c0v.y);
        *(__half2*)(g.out16a + idx) = __floats2half2_rn((1.f - s0) * x0v.x, (1.f - s1) * x0v.y);
        *(__half2*)(g.out16b + idx) = __floats2half2_rn(s0 * xlv.x, s1 * xlv.y);
    } else if (MODE == MODE_UR) {
        if (col < Hdim) {
            float2 b = *(const float2*)(g.bias0 + c512);
            *(__half2*)(g.out16a + idx) = __floats2half2_rn(sigmoidf_(v0 + b.x),
                                                            sigmoidf_(v1 + b.y));
        } else {
            float2 b = *(const float2*)(g.bias1 + c512);
            float2 h = *(const float2*)(g.hx + idx);
            *(__half2*)(g.out16b + idx) = __floats2half2_rn(sigmoidf_(v0 + b.x) * h.x,
                                                            sigmoidf_(v1 + b.y) * h.y);
        }
    } else { // MODE_K
        float2 b = *(const float2*)(g.bias0 + c512);
        float2 u = h2f(g.U + idx);
        float2 h = *(const float2*)(g.hx + idx);
        float k0 = tanhf(v0 + b.x), k1 = tanhf(v1 + b.y);
        float r0 = (1.f - u.x) * k0 + u.x * h.x;
        float r1 = (1.f - u.y) * k1 + u.y * h.y;
        *(float2*)(g.out0 + idx) = make_float2(r0, r1);
        *(__half2*)(g.out16a + idx) = __floats2half2_rn(r0, r1);
    }
}

// 512 threads: each copies 4 A-chunks + 2 B-chunks of 16B (8 fp16) per stage
__device__ __forceinline__ void issue_stage(const GemmArgs& g, int kb, int tid,
                                            int rowBase, int colBase, char* sm) {
    int c = tid & 7;                 // 16B chunk within 128B row
    int r = tid >> 3;                // 0..63
    const __half* asrc = g.A[kb >> 3] + (size_t)(rowBase + r) * 512 + (kb & 7) * 64 + c * 8;
    const __half* bsrc = g.Bt + (size_t)(colBase + r) * g.ldB + kb * 64 + c * 8;
#pragma unroll
    for (int rr = 0; rr < 4; ++rr)
        cp_async16(sm + (r + 64 * rr) * AROW_B + c * 16, asrc + (size_t)(64 * rr) * 512);
#pragma unroll
    for (int rr = 0; rr < 2; ++rr)
        cp_async16(sm + (A_ROWS + r + 64 * rr) * AROW_B + c * 16,
                   bsrc + (size_t)(64 * rr) * g.ldB);
}

// warp tile 64(M) x 32(N), BK=64: 4 k16-steps; 6 ldmatrix.x4 + 16 mma per step
__device__ __forceinline__ void compute_stage(uint32_t base, uint32_t a_off, uint32_t b_off,
                                              float (&acc)[4][4][4]) {
#pragma unroll
    for (int kk = 0; kk < 4; ++kk) {
        uint32_t a[4][4];
        uint32_t b[2][4];
#pragma unroll
        for (int i = 0; i < 4; ++i)
            ldsm_x4(a[i], base + a_off + kk * 32 + i * (16 * AROW_B));
#pragma unroll
        for (int jj = 0; jj < 2; ++jj)
            ldsm_x4(b[jj], base + b_off + kk * 32 + jj * (16 * AROW_B));
#pragma unroll
        for (int i = 0; i < 4; ++i)
#pragma unroll
            for (int j = 0; j < 4; ++j)
                mma_f16(acc[i][j], a[i], b[j >> 1][(j & 1) * 2], b[j >> 1][(j & 1) * 2 + 1]);
    }
}

template <int MODE>
__global__ void __launch_bounds__(512, 1) gemm_cp(GemmArgs args, int kblocks) {
    extern __shared__ char sm[];
    uint32_t su = smem_u32(sm);
    int tid = threadIdx.x;
    int warp = tid >> 5, lane = tid & 31;
    int MW = (warp & 3) * 64, NW = (warp >> 2) * 32;
    int g = lane >> 2, c = lane & 3;
    // grid: x = N tile (fast), y = M tile
    int rowBase = blockIdx.y * 256, colBase = blockIdx.x * 128;

    // ldmatrix lane address offsets (bytes within stage)
    uint32_t a_off = (uint32_t)((MW + (lane & 15)) * AROW_B + (lane >> 4) * 16);
    uint32_t b_off = (uint32_t)((A_ROWS + NW + (lane & 7) + ((lane >> 4) << 3)) * AROW_B
                                + ((lane >> 3) & 1) * 16);

    float acc[4][4][4];
#pragma unroll
    for (int i = 0; i < 4; ++i)
#pragma unroll
        for (int j = 0; j < 4; ++j)
#pragma unroll
            for (int e = 0; e < 4; ++e) acc[i][j][e] = 0.0f;

    issue_stage(args, 0, tid, rowBase, colBase, sm);
    CP_COMMIT();
    if (kblocks > 1) issue_stage(args, 1, tid, rowBase, colBase, sm + STAGE_B);
    CP_COMMIT();

    int stage = 0;
    for (int kb = 0; kb < kblocks; ++kb) {
        CP_WAIT1();
        __syncthreads();
        if (kb + 2 < kblocks) {
            int ns = stage + 2;
            if (ns >= NSTAGE) ns -= NSTAGE;
            issue_stage(args, kb + 2, tid, rowBase, colBase, sm + ns * STAGE_B);
        }
        CP_COMMIT();
        compute_stage(su + stage * STAGE_B, a_off, b_off, acc);
        if (++stage == NSTAGE) stage = 0;
    }

    // epilogue
#pragma unroll
    for (int i = 0; i < 4; ++i) {
#pragma unroll
        for (int j = 0; j < 4; ++j) {
            int row = rowBase + MW + i * 16 + g;
            int col = colBase + NW + j * 8 + 2 * c;
            epi<MODE>(args, row, col, acc[i][j][0], acc[i][j][1]);
            epi<MODE>(args, row + 8, col, acc[i][j][2], acc[i][j][3]);
        }
    }
}

// ---------------- fused weight transpose (fp32 -> fp16 [n][k]) ------------------
struct TransJobs {
    const float* src[7];
    __half* dst[7];
    int dstld[7];
    int ktiles[7];
    int tileofs[7];
};

__global__ void transposeAll(TransJobs J) {
    __shared__ float t[32][33];
    int bid = blockIdx.x;
    int job = 0;
#pragma unroll
    for (int i = 1; i < 7; ++i)
        if (bid >= J.tileofs[i]) job = i;
    int local = bid - J.tileofs[job];
    int kt = J.ktiles[job];
    int kb = (local % kt) * 32;
    int nb = (local / kt) * 32;
    const float* src = J.src[job];
    __half* dst = J.dst[job];
    int dstld = J.dstld[job];
    int tx = threadIdx.x, ty = threadIdx.y;
#pragma unroll
    for (int i = 0; i < 32; i += 8)
        t[ty + i][tx] = src[(size_t)(kb + ty + i) * 512 + nb + tx];
    __syncthreads();
#pragma unroll
    for (int i = 0; i < 32; i += 8)
        dst[(size_t)(nb + ty + i) * dstld + kb + tx] = __float2half_rn(t[tx][ty + i]);
}

// ---------------- fp32 -> fp16 bulk convert -------------------------------------
__global__ void f2h8(const float* __restrict__ src, __half* __restrict__ dst, int n) {
    int i = (blockIdx.x * blockDim.x + threadIdx.x) * 8;
    if (i >= n) return;
    float4 v0 = *(const float4*)(src + i);
    float4 v1 = *(const float4*)(src + i + 4);
    __half2 h[4] = {__floats2half2_rn(v0.x, v0.y), __floats2half2_rn(v0.z, v0.w),
                    __floats2half2_rn(v1.x, v1.y), __floats2half2_rn(v1.z, v1.w)};
    *(uint4*)(dst + i) = *(uint4*)h;
}

// ---------------- host -----------------------------------------------------------
template <int MODE>
static void run_gemm(const GemmArgs& a, int M, int nTiles, int kblocks) {
    cudaFuncSetAttribute(gemm_cp<MODE>, cudaFuncAttributeMaxDynamicSharedMemorySize,
                         SMEM_BYTES);
    dim3 grid(nTiles, M / 256);      // N tiles fastest -> A reuse within a wave
    gemm_cp<MODE><<<grid, 512, SMEM_BYTES>>>(a, kblocks);
}

extern "C" void kernel_launch(void* const* d_in, const int* in_sizes, int n_in,
                              void* d_out, int out_size) {
    const float* edge = (const float*)d_in[0];
    const float* node = (const float*)d_in[1];
    const float* W_xi = (const float*)d_in[2];
    const float* b_xi = (const float*)d_in[3];
    const float* W_u  = (const float*)d_in[4];
    const float* b_u  = (const float*)d_in[5];
    const float* W_r  = (const float*)d_in[6];
    const float* b_r  = (const float*)d_in[7];
    const float* W_k  = (const float*)d_in[8];
    const float* b_k  = (const float*)d_in[9];
    float* hx = (float*)d_out;

    __half *P, *C0, *U;
    __half *E16, *N16, *X0H16, *XTH16, *RH16, *HX16, *W1T, *WpT, *W3T, *WurT, *WkT;
    cudaGetSymbolAddress((void**)&P,     g_P);
    cudaGetSymbolAddress((void**)&C0,    g_C0);
    cudaGetSymbolAddress((void**)&U,     g_U);
    cudaGetSymbolAddress((void**)&E16,   g_E16);
    cudaGetSymbolAddress((void**)&N16,   g_N16);
    cudaGetSymbolAddress((void**)&X0H16, g_X0H16);
    cudaGetSymbolAddress((void**)&XTH16, g_XTH16);
    cudaGetSymbolAddress((void**)&RH16,  g_RH16);
    cudaGetSymbolAddress((void**)&HX16,  g_HX16);
    cudaGetSymbolAddress((void**)&W1T,   g_W1T);
    cudaGetSymbolAddress((void**)&WpT,   g_WpT);
    cudaGetSymbolAddress((void**)&W3T,   g_W3T);
    cudaGetSymbolAddress((void**)&WurT,  g_WurT);
    cudaGetSymbolAddress((void**)&WkT,   g_WkT);

    cudaMemsetAsync(d_out, 0, (size_t)out_size * sizeof(float), 0);
    cudaMemsetAsync(HX16, 0, (size_t)NH * sizeof(__half), 0);

    // fp32 -> fp16 for edge / node (incl. x0)
    {
        int nE = Lsteps * NH;
        int nN = (Lsteps + 1) * NH;
        f2h8<<<(nE / 8 + 255) / 256, 256>>>(edge, E16, nE);
        f2h8<<<(nN / 8 + 255) / 256, 256>>>(node, N16, nN);
    }

    // fused weight transpose -> fp16 [n][k]
    {
        TransJobs J;
        const float* srcs[7] = {W_xi, W_xi + 512 * 512, W_xi + 1536 * 512,
                                W_xi + 1024 * 512, W_u, W_r, W_k};
        __half* dsts[7] = {W1T, WpT, WpT + 512, W3T, WurT,
                           WurT + (size_t)512 * 1536, WkT};
        int lds[7] = {512, 1024, 1024, 512, 1536, 1536, 1536};
        int kts[7] = {16, 16, 16, 16, 48, 48, 48};
        int ofs = 0;
        for (int i = 0; i < 7; ++i) {
            J.src[i] = srcs[i]; J.dst[i] = dsts[i]; J.dstld[i] = lds[i];
            J.ktiles[i] = kts[i]; J.tileofs[i] = ofs;
            ofs += kts[i] * 16;
        }
        transposeAll<<<ofs, dim3(32, 8)>>>(J);
    }

    const __half* x016 = N16 + (size_t)Lsteps * NH;

    // PRE: P[l] = el @ W2 + xl @ W4   (M = L*N, K = 1024, Nout = 512) -> fp16
    {
        GemmArgs a = {};
        a.A[0] = E16; a.A[1] = N16;
        a.Bt = WpT; a.ldB = 1024;
        a.out16a = P;
        run_gemm<MODE_PRE>(a, Lsteps * Nrows, 4, 16);
    }
    // C0 = x0 @ W3 + b_xi -> fp16
    {
        GemmArgs a = {};
        a.A[0] = x016;
        a.Bt = W3T; a.ldB = 512;
        a.bias0 = b_xi; a.out16a = C0;
        run_gemm<MODE_C0>(a, Nrows, 4, 8);
    }

    for (int l = 0; l < Lsteps; ++l) {
        // xi gate -> X0H16, XTH16
        {
            GemmArgs a = {};
            a.A[0] = HX16;
            a.Bt = W1T; a.ldB = 512;
            a.P = P + (size_t)l * NH; a.C0 = C0;
            a.x0 = x016; a.xl = N16 + (size_t)l * NH;
            a.out16a = X0H16; a.out16b = XTH16;
            run_gemm<MODE_XI>(a, Nrows, 4, 8);
        }
        // fused u | r -> U (fp16), RH16
        {
            GemmArgs a = {};
            a.A[0] = HX16; a.A[1] = X0H16; a.A[2] = XTH16;
            a.Bt = WurT; a.ldB = 1536;
            a.bias0 = b_u; a.bias1 = b_r; a.hx = hx;
            a.out16a = U; a.out16b = RH16;
            run_gemm<MODE_UR>(a, Nrows, 8, 24);
        }
        // k + state update -> hx (fp32) + HX16
        {
            GemmArgs a = {};
            a.A[0] = X0H16; a.A[1] = XTH16; a.A[2] = RH16;
            a.Bt = WkT; a.ldB = 1536;
            a.bias0 = b_k; a.U = U; a.hx = hx;
            a.out0 = hx; a.out16a = HX16;
            run_gemm<MODE_K>(a, Nrows, 4, 24);
        }
    }
}

// round 8
// speedup vs baseline: 1.0083x; 1.0083x over previous
#include <cuda_runtime.h>
#include <cuda_fp16.h>
#include <math.h>
#include <stdint.h>

// Problem constants
#define Hdim 512
#define Lsteps 16
#define Nrows 8192
#define NH (Nrows * Hdim)

// ---------------- scratch (device globals) ------------------------------------
__device__ __half g_P[Lsteps * (size_t)NH];  // precomputed el@W2 + xl@W4 (fp16)
__device__ __half g_C0[NH];                  // x0@W3 + b_xi (fp16)
__device__ __half g_U[NH];                   // u gate (fp16)
__device__ __half g_E16[Lsteps * (size_t)NH];
__device__ __half g_N16[(Lsteps + 1) * (size_t)NH];
__device__ __half g_X0H16[NH];
__device__ __half g_XTH16[NH];
__device__ __half g_RH16[NH];
__device__ __half g_HX16[NH];
// fp16 transposed weights [n][k]
__device__ __half g_W1T[512 * 512];
__device__ __half g_WpT[512 * 1024];
__device__ __half g_W3T[512 * 512];
__device__ __half g_WurT[1024 * 1536];
__device__ __half g_WkT[512 * 1536];
// global barrier state
__device__ unsigned g_barCount = 0;
__device__ unsigned g_barGen = 0;

// ---------------- helpers -------------------------------------------------------
__device__ __forceinline__ uint32_t smem_u32(const void* p) {
    uint32_t a;
    asm("{ .reg .u64 t; cvta.to.shared.u64 t, %1; cvt.u32.u64 %0, t; }" : "=r"(a) : "l"(p));
    return a;
}
__device__ __forceinline__ void cp_async16(void* dst, const void* src) {
    asm volatile("cp.async.cg.shared.global [%0], [%1], 16;"
                 :: "r"(smem_u32(dst)), "l"(src) : "memory");
}
#define CP_COMMIT() asm volatile("cp.async.commit_group;" ::: "memory")
#define CP_WAIT1()  asm volatile("cp.async.wait_group 1;" ::: "memory")
#define CP_WAIT0()  asm volatile("cp.async.wait_group 0;" ::: "memory")

__device__ __forceinline__ void ldsm_x4(uint32_t (&r)[4], uint32_t addr) {
    asm volatile("ldmatrix.sync.aligned.m8n8.x4.shared.b16 {%0,%1,%2,%3}, [%4];"
                 : "=r"(r[0]), "=r"(r[1]), "=r"(r[2]), "=r"(r[3]) : "r"(addr));
}
__device__ __forceinline__ void mma_f16(float (&d)[4], const uint32_t (&a)[4],
                                        uint32_t b0, uint32_t b1) {
    asm volatile(
        "mma.sync.aligned.m16n8k16.row.col.f32.f16.f16.f32 "
        "{%0,%1,%2,%3}, {%4,%5,%6,%7}, {%8,%9}, {%0,%1,%2,%3};"
        : "+f"(d[0]), "+f"(d[1]), "+f"(d[2]), "+f"(d[3])
        : "r"(a[0]), "r"(a[1]), "r"(a[2]), "r"(a[3]), "r"(b0), "r"(b1));
}
__device__ __forceinline__ float sigmoidf_(float x) { return 1.0f / (1.0f + expf(-x)); }

// grid-wide barrier (all gridDim.x CTAs participate)
__device__ __forceinline__ void grid_barrier(unsigned ncta) {
    __syncthreads();
    if (threadIdx.x == 0) {
        __threadfence();
        unsigned g = *(volatile unsigned*)&g_barGen;
        if (atomicAdd(&g_barCount, 1u) == ncta - 1u) {
            g_barCount = 0;
            __threadfence();
            atomicAdd(&g_barGen, 1u);
        } else {
            while (*(volatile unsigned*)&g_barGen == g)
                asm volatile("nanosleep.u32 64;");
        }
        __threadfence();
    }
    __syncthreads();
}

// ---------------- GEMM config ---------------------------------------------------
// CTA 128x128x64 fp16, 8 warps (warp tile 64x32), 3-stage cp.async pipeline.
#define AROW_B 144                      // 64 fp16 (128B) + 16B pad
#define STAGE_A_B (128 * AROW_B)        // 18432 B
#define STAGE_B (2 * STAGE_A_B)         // 36864 B (A rows then B rows)
#define NSTAGE 3
#define SMEM_BYTES (NSTAGE * STAGE_B)   // 110592

struct GemmArgs {
    const __half* A[3];         // K blocks of 512 (row-major fp16, ld = 512)
    const __half* Bt;           // transposed fp16 weights [Ntot][Ktot]
    int ldB;
    const __half* P;
    const __half* C0;
    const __half* x0;
    const __half* xl;
    const float* bias0;
    const float* bias1;
    const float* hx;
    const __half* U;
    float* out0;
    __half* out16a;
    __half* out16b;
};

#define MODE_PRE 0
#define MODE_C0  1
#define MODE_XI  2
#define MODE_UR  3
#define MODE_K   4

__device__ __forceinline__ float2 h2f(const __half* p) {
    return __half22float2(*(const __half2*)p);
}

template <int MODE>
__device__ __forceinline__ void epi(const GemmArgs& g, int row, int col, float v0, float v1) {
    int c512 = col & 511;
    size_t idx = (size_t)row * Hdim + c512;
    if (MODE == MODE_PRE) {
        *(__half2*)(g.out16a + idx) = __floats2half2_rn(v0, v1);
    } else if (MODE == MODE_C0) {
        float2 b = *(const float2*)(g.bias0 + c512);
        *(__half2*)(g.out16a + idx) = __floats2half2_rn(v0 + b.x, v1 + b.y);
    } else if (MODE == MODE_XI) {
        float2 p   = h2f(g.P  + idx);
        float2 c0v = h2f(g.C0 + idx);
        float2 x0v = h2f(g.x0 + idx);
        float2 xlv = h2f(g.xl + idx);
        float s0 = sigmoidf_(v0 + p.x + c0v.x);
        float s1 = sigmoidf_(v1 + p.y + c0v.y);
        *(__half2*)(g.out16a + idx) = __floats2half2_rn((1.f - s0) * x0v.x, (1.f - s1) * x0v.y);
        *(__half2*)(g.out16b + idx) = __floats2half2_rn(s0 * xlv.x, s1 * xlv.y);
    } else if (MODE == MODE_UR) {
        if (col < Hdim) {
            float2 b = *(const float2*)(g.bias0 + c512);
            *(__half2*)(g.out16a + idx) = __floats2half2_rn(sigmoidf_(v0 + b.x),
                                                            sigmoidf_(v1 + b.y));
        } else {
            float2 b = *(const float2*)(g.bias1 + c512);
            float2 h = __ldcg((const float2*)(g.hx + idx));   // fresh across phases
            *(__half2*)(g.out16b + idx) = __floats2half2_rn(sigmoidf_(v0 + b.x) * h.x,
                                                            sigmoidf_(v1 + b.y) * h.y);
        }
    } else { // MODE_K
        float2 b = *(const float2*)(g.bias0 + c512);
        float2 u = __half22float2(__ldcg((const __half2*)(g.U + idx)));
        float2 h = __ldcg((const float2*)(g.hx + idx));
        float k0 = tanhf(v0 + b.x), k1 = tanhf(v1 + b.y);
        float r0 = (1.f - u.x) * k0 + u.x * h.x;
        float r1 = (1.f - u.y) * k1 + u.y * h.y;
        *(float2*)(g.out0 + idx) = make_float2(r0, r1);
        *(__half2*)(g.out16a + idx) = __floats2half2_rn(r0, r1);
    }
}

// 256 threads: each copies 4 A-chunks + 4 B-chunks of 16B (8 fp16) per stage
__device__ __forceinline__ void issue_stage(const GemmArgs& g, int kb, int tid,
                                            int rowBase, int colBase, char* sm) {
    int c = tid & 7;
    int r = tid >> 3;                // 0..31
    const __half* asrc = g.A[kb >> 3] + (size_t)(rowBase + r) * 512 + (kb & 7) * 64 + c * 8;
    const __half* bsrc = g.Bt + (size_t)(colBase + r) * g.ldB + kb * 64 + c * 8;
    char* As = sm;
    char* Bs = sm + STAGE_A_B;
#pragma unroll
    for (int rr = 0; rr < 4; ++rr) {
        cp_async16(As + (r + 32 * rr) * AROW_B + c * 16, asrc + (size_t)(32 * rr) * 512);
        cp_async16(Bs + (r + 32 * rr) * AROW_B + c * 16, bsrc + (size_t)(32 * rr) * g.ldB);
    }
}

// warp tile 64(M) x 32(N), BK=64
__device__ __forceinline__ void compute_stage(uint32_t base, uint32_t a_off, uint32_t b_off,
                                              float (&acc)[4][4][4]) {
#pragma unroll
    for (int kk = 0; kk < 4; ++kk) {
        uint32_t a[4][4];
        uint32_t b[2][4];
#pragma unroll
        for (int i = 0; i < 4; ++i)
            ldsm_x4(a[i], base + a_off + kk * 32 + i * (16 * AROW_B));
#pragma unroll
        for (int jj = 0; jj < 2; ++jj)
            ldsm_x4(b[jj], base + b_off + kk * 32 + jj * (16 * AROW_B));
#pragma unroll
        for (int i = 0; i < 4; ++i)
#pragma unroll
            for (int j = 0; j < 4; ++j)
                mma_f16(acc[i][j], a[i], b[j >> 1][(j & 1) * 2], b[j >> 1][(j & 1) * 2 + 1]);
    }
}

// one 128x128 output tile (R6-validated engine)
template <int MODE>
__device__ __forceinline__ void gemm_tile(const GemmArgs& args, int rowBase, int colBase,
                                          int kblocks, char* sm) {
    CP_WAIT0();            // protect smem reuse across tiles
    __syncthreads();
    uint32_t su = smem_u32(sm);
    int tid = threadIdx.x;
    int warp = tid >> 5, lane = tid & 31;
    int MW = (warp & 1) * 64, NW = (warp >> 1) * 32;
    int g = lane >> 2, c = lane & 3;

    uint32_t a_off = (uint32_t)((MW + (lane & 15)) * AROW_B + (lane >> 4) * 16);
    uint32_t b_off = (uint32_t)(STAGE_A_B + (NW + (lane & 7) + ((lane >> 4) << 3)) * AROW_B
                                + ((lane >> 3) & 1) * 16);

    float acc[4][4][4];
#pragma unroll
    for (int i = 0; i < 4; ++i)
#pragma unroll
        for (int j = 0; j < 4; ++j)
#pragma unroll
            for (int e = 0; e < 4; ++e) acc[i][j][e] = 0.0f;

    issue_stage(args, 0, tid, rowBase, colBase, sm);
    CP_COMMIT();
    if (kblocks > 1) issue_stage(args, 1, tid, rowBase, colBase, sm + STAGE_B);
    CP_COMMIT();

    int stage = 0;
    for (int kb = 0; kb < kblocks; ++kb) {
        CP_WAIT1();
        __syncthreads();
        if (kb + 2 < kblocks) {
            int ns = stage + 2;
            if (ns >= NSTAGE) ns -= NSTAGE;
            issue_stage(args, kb + 2, tid, rowBase, colBase, sm + ns * STAGE_B);
        }
        CP_COMMIT();
        compute_stage(su + stage * STAGE_B, a_off, b_off, acc);
        if (++stage == NSTAGE) stage = 0;
    }

#pragma unroll
    for (int i = 0; i < 4; ++i) {
#pragma unroll
        for (int j = 0; j < 4; ++j) {
            int row = rowBase + MW + i * 16 + g;
            int col = colBase + NW + j * 8 + 2 * c;
            epi<MODE>(args, row, col, acc[i][j][0], acc[i][j][1]);
            epi<MODE>(args, row + 8, col, acc[i][j][2], acc[i][j][3]);
        }
    }
}

// standalone GEMM kernel (PRE / C0)
template <int MODE>
__global__ void __launch_bounds__(256, 2) gemm_cp(GemmArgs args, int kblocks) {
    extern __shared__ char sm[];
    gemm_tile<MODE>(args, blockIdx.y * 128, blockIdx.x * 128, kblocks, sm);
}

// ---------------- persistent recurrence kernel ----------------------------------
struct RecPtrs {
    const __half *N16, *P, *C0, *x0;
    __half *HX16, *X0H16, *XTH16, *RH16, *U;
    const __half *W1T, *WurT, *WkT;
    const float *b_u, *b_r, *b_k;
    float* hx;
};

__global__ void __launch_bounds__(256, 2) recurrence_pk(RecPtrs R) {
    extern __shared__ char sm[];
    unsigned ncta = gridDim.x;
    int bid = blockIdx.x;

    for (int l = 0; l < Lsteps; ++l) {
        {   // XI: 256 tiles (M=8192, N=512, K=512)
            GemmArgs a = {};
            a.A[0] = R.HX16;
            a.Bt = R.W1T; a.ldB = 512;
            a.P = R.P + (size_t)l * NH; a.C0 = R.C0;
            a.x0 = R.x0; a.xl = R.N16 + (size_t)l * NH;
            a.out16a = R.X0H16; a.out16b = R.XTH16;
            for (int t = bid; t < 256; t += ncta)
                gemm_tile<MODE_XI>(a, (t >> 2) * 128, (t & 3) * 128, 8, sm);
        }
        grid_barrier(ncta);
        {   // UR: 512 tiles (N=1024, K=1536)
            GemmArgs a = {};
            a.A[0] = R.HX16; a.A[1] = R.X0H16; a.A[2] = R.XTH16;
            a.Bt = R.WurT; a.ldB = 1536;
            a.bias0 = R.b_u; a.bias1 = R.b_r; a.hx = R.hx;
            a.out16a = R.U; a.out16b = R.RH16;
            for (int t = bid; t < 512; t += ncta)
                gemm_tile<MODE_UR>(a, (t >> 3) * 128, (t & 7) * 128, 24, sm);
        }
        grid_barrier(ncta);
        {   // K: 256 tiles (N=512, K=1536)
            GemmArgs a = {};
            a.A[0] = R.X0H16; a.A[1] = R.XTH16; a.A[2] = R.RH16;
            a.Bt = R.WkT; a.ldB = 1536;
            a.bias0 = R.b_k; a.U = R.U; a.hx = R.hx;
            a.out0 = R.hx; a.out16a = R.HX16;
            for (int t = bid; t < 256; t += ncta)
                gemm_tile<MODE_K>(a, (t >> 2) * 128, (t & 3) * 128, 24, sm);
        }
        grid_barrier(ncta);
    }
}

// ---------------- fused weight transpose (fp32 -> fp16 [n][k]) ------------------
struct TransJobs {
    const float* src[7];
    __half* dst[7];
    int dstld[7];
    int ktiles[7];
    int tileofs[7];
};

__global__ void transposeAll(TransJobs J) {
    __shared__ float t[32][33];
    int bid = blockIdx.x;
    int job = 0;
#pragma unroll
    for (int i = 1; i < 7; ++i)
        if (bid >= J.tileofs[i]) job = i;
    int local = bid - J.tileofs[job];
    int kt = J.ktiles[job];
    int kb = (local % kt) * 32;
    int nb = (local / kt) * 32;
    const float* src = J.src[job];
    __half* dst = J.dst[job];
    int dstld = J.dstld[job];
    int tx = threadIdx.x, ty = threadIdx.y;
#pragma unroll
    for (int i = 0; i < 32; i += 8)
        t[ty + i][tx] = src[(size_t)(kb + ty + i) * 512 + nb + tx];
    __syncthreads();
#pragma unroll
    for (int i = 0; i < 32; i += 8)
        dst[(size_t)(nb + ty + i) * dstld + kb + tx] = __float2half_rn(t[tx][ty + i]);
}

// ---------------- fp32 -> fp16 bulk convert -------------------------------------
__global__ void f2h8(const float* __restrict__ src, __half* __restrict__ dst, int n) {
    int i = (blockIdx.x * blockDim.x + threadIdx.x) * 8;
    if (i >= n) return;
    float4 v0 = *(const float4*)(src + i);
    float4 v1 = *(const float4*)(src + i + 4);
    __half2 h[4] = {__floats2half2_rn(v0.x, v0.y), __floats2half2_rn(v0.z, v0.w),
                    __floats2half2_rn(v1.x, v1.y), __floats2half2_rn(v1.z, v1.w)};
    *(uint4*)(dst + i) = *(uint4*)h;
}

// ---------------- host -----------------------------------------------------------
template <int MODE>
static void run_gemm(const GemmArgs& a, int M, int nTiles, int kblocks) {
    cudaFuncSetAttribute(gemm_cp<MODE>, cudaFuncAttributeMaxDynamicSharedMemorySize,
                         SMEM_BYTES);
    dim3 grid(nTiles, M / 128);
    gemm_cp<MODE><<<grid, 256, SMEM_BYTES>>>(a, kblocks);
}

extern "C" void kernel_launch(void* const* d_in, const int* in_sizes, int n_in,
                              void* d_out, int out_size) {
    const float* edge = (const float*)d_in[0];
    const float* node = (const float*)d_in[1];
    const float* W_xi = (const float*)d_in[2];
    const float* b_xi = (const float*)d_in[3];
    const float* W_u  = (const float*)d_in[4];
    const float* b_u  = (const float*)d_in[5];
    const float* W_r  = (const float*)d_in[6];
    const float* b_r  = (const float*)d_in[7];
    const float* W_k  = (const float*)d_in[8];
    const float* b_k  = (const float*)d_in[9];
    float* hx = (float*)d_out;

    __half *P, *C0, *U;
    __half *E16, *N16, *X0H16, *XTH16, *RH16, *HX16, *W1T, *WpT, *W3T, *WurT, *WkT;
    cudaGetSymbolAddress((void**)&P,     g_P);
    cudaGetSymbolAddress((void**)&C0,    g_C0);
    cudaGetSymbolAddress((void**)&U,     g_U);
    cudaGetSymbolAddress((void**)&E16,   g_E16);
    cudaGetSymbolAddress((void**)&N16,   g_N16);
    cudaGetSymbolAddress((void**)&X0H16, g_X0H16);
    cudaGetSymbolAddress((void**)&XTH16, g_XTH16);
    cudaGetSymbolAddress((void**)&RH16,  g_RH16);
    cudaGetSymbolAddress((void**)&HX16,  g_HX16);
    cudaGetSymbolAddress((void**)&W1T,   g_W1T);
    cudaGetSymbolAddress((void**)&WpT,   g_WpT);
    cudaGetSymbolAddress((void**)&W3T,   g_W3T);
    cudaGetSymbolAddress((void**)&WurT,  g_WurT);
    cudaGetSymbolAddress((void**)&WkT,   g_WkT);

    cudaMemsetAsync(d_out, 0, (size_t)out_size * sizeof(float), 0);
    cudaMemsetAsync(HX16, 0, (size_t)NH * sizeof(__half), 0);

    // fp32 -> fp16 for edge / node (incl. x0)
    {
        int nE = Lsteps * NH;
        int nN = (Lsteps + 1) * NH;
        f2h8<<<(nE / 8 + 255) / 256, 256>>>(edge, E16, nE);
        f2h8<<<(nN / 8 + 255) / 256, 256>>>(node, N16, nN);
    }

    // fused weight transpose -> fp16 [n][k]
    {
        TransJobs J;
        const float* srcs[7] = {W_xi, W_xi + 512 * 512, W_xi + 1536 * 512,
                                W_xi + 1024 * 512, W_u, W_r, W_k};
        __half* dsts[7] = {W1T, WpT, WpT + 512, W3T, WurT,
                           WurT + (size_t)512 * 1536, WkT};
        int lds[7] = {512, 1024, 1024, 512, 1536, 1536, 1536};
        int kts[7] = {16, 16, 16, 16, 48, 48, 48};
        int ofs = 0;
        for (int i = 0; i < 7; ++i) {
            J.src[i] = srcs[i]; J.dst[i] = dsts[i]; J.dstld[i] = lds[i];
            J.ktiles[i] = kts[i]; J.tileofs[i] = ofs;
            ofs += kts[i] * 16;
        }
        transposeAll<<<ofs, dim3(32, 8)>>>(J);
    }

    const __half* x016 = N16 + (size_t)Lsteps * NH;

    // PRE: P[l] = el @ W2 + xl @ W4   (M = L*N, K = 1024, Nout = 512) -> fp16
    {
        GemmArgs a = {};
        a.A[0] = E16; a.A[1] = N16;
        a.Bt = WpT; a.ldB = 1024;
        a.out16a = P;
        run_gemm<MODE_PRE>(a, Lsteps * Nrows, 4, 16);
    }
    // C0 = x0 @ W3 + b_xi -> fp16
    {
        GemmArgs a = {};
        a.A[0] = x016;
        a.Bt = W3T; a.ldB = 512;
        a.bias0 = b_xi; a.out16a = C0;
        run_gemm<MODE_C0>(a, Nrows, 4, 8);
    }

    // persistent recurrence: all 16 steps, grid-wide barriers between phases
    {
        cudaFuncSetAttribute(recurrence_pk, cudaFuncAttributeMaxDynamicSharedMemorySize,
                             SMEM_BYTES);
        int dev = 0;
        cudaGetDevice(&dev);
        int smCount = 0;
        cudaDeviceGetAttribute(&smCount, cudaDevAttrMultiProcessorCount, dev);
        int occ = 0;
        cudaOccupancyMaxActiveBlocksPerMultiprocessor(&occ, recurrence_pk, 256, SMEM_BYTES);
        if (occ < 1) occ = 1;
        if (occ > 2) occ = 2;
        int ncta = smCount * occ;

        RecPtrs R;
        R.N16 = N16; R.P = P; R.C0 = C0; R.x0 = x016;
        R.HX16 = HX16; R.X0H16 = X0H16; R.XTH16 = XTH16; R.RH16 = RH16; R.U = U;
        R.W1T = W1T; R.WurT = WurT; R.WkT = WkT;
        R.b_u = b_u; R.b_r = b_r; R.b_k = b_k;
        R.hx = hx;
        recurrence_pk<<<ncta, 256, SMEM_BYTES>>>(R);
    }
}

// round 9
// speedup vs baseline: 1.2029x; 1.1930x over previous
#include <cuda_runtime.h>
#include <cuda_fp16.h>
#include <math.h>
#include <stdint.h>

// Problem constants
#define Hdim 512
#define Lsteps 16
#define Nrows 8192
#define NH (Nrows * Hdim)

// Panel: 128 rows x 64 fp16, 144B pitch (16B pad) = exact smem stage layout
#define PANEL_H 9216                    // halves per panel
#define PANEL_BYTES 18432
#define STG_BYTES 36864                 // A panel + B panel
#define NSTAGE 3
#define SMEM_BYTES (64 + NSTAGE * STG_BYTES)   // 110656

// ---------------- scratch (device globals) ------------------------------------
__device__ __half g_P[Lsteps * (size_t)NH];     // row-major (epilogue operand)
__device__ __half g_C0[NH];                     // row-major
__device__ __half g_U[NH];                      // row-major
// panelized A-operand tensors
__device__ __half g_E16[75497472];              // 1024 tiles * 8 panels
__device__ __half g_N16[80216064];              // 1088 tiles * 8 panels (17 layers)
__device__ __half g_X0H16[4718592];             // 64 tiles * 8 panels
__device__ __half g_XTH16[4718592];
__device__ __half g_RH16[4718592];
__device__ __half g_HX16[4718592];
// panelized weights
__device__ __half g_W1T[294912];                // 4 ntiles * 8 kpanels
__device__ __half g_WpT[589824];                // 4 * 16
__device__ __half g_W3T[294912];                // 4 * 8
__device__ __half g_WurT[1769472];              // 8 * 24
__device__ __half g_WkT[884736];                // 4 * 24

// ---------------- helpers -------------------------------------------------------
__device__ __forceinline__ uint32_t smem_u32(const void* p) {
    uint32_t a;
    asm("{ .reg .u64 t; cvta.to.shared.u64 t, %1; cvt.u32.u64 %0, t; }" : "=r"(a) : "l"(p));
    return a;
}
#define MBARRIER_INIT(addr, cnt) \
    asm volatile("mbarrier.init.shared.b64 [%0], %1;" :: "r"((uint32_t)(addr)), "r"((uint32_t)(cnt)) : "memory")
#define MBARRIER_EXPECT_TX(addr, tx) \
    asm volatile("mbarrier.arrive.expect_tx.shared.b64 _, [%0], %1;" :: "r"((uint32_t)(addr)), "r"((uint32_t)(tx)) : "memory")
#define MBARRIER_WAIT_PARITY(addr, par) do { \
    uint32_t _m = (uint32_t)(addr); uint32_t _p = (uint32_t)(par); uint32_t _d; \
    asm volatile("{\n\t.reg .pred p;\n\t" \
        "mbarrier.try_wait.parity.acquire.cta.shared::cta.b64 p, [%1], %2;\n\t" \
        "selp.b32 %0, 1, 0, p;\n\t}" : "=r"(_d) : "r"(_m), "r"(_p) : "memory"); \
    if (!_d) { \
        asm volatile("{\n\t.reg .pred P1;\n\t" \
            "WL_%=:\n\t" \
            "mbarrier.try_wait.parity.acquire.cta.shared::cta.b64 P1, [%0], %1, 0x989680;\n\t" \
            "@P1 bra.uni WD_%=;\n\t" \
            "bra.uni WL_%=;\n\t" \
            "WD_%=:\n\t}" :: "r"(_m), "r"(_p) : "memory"); \
    } } while (0)

__device__ __forceinline__ void bulk_cp(uint32_t dst, const void* src, uint32_t bytes,
                                        uint32_t mbar) {
    asm volatile(
        "cp.async.bulk.shared::cluster.global.mbarrier::complete_tx::bytes "
        "[%0], [%1], %2, [%3];"
        :: "r"(dst), "l"(src), "r"(bytes), "r"(mbar) : "memory");
}

__device__ __forceinline__ void ldsm_x4(uint32_t (&r)[4], uint32_t addr) {
    asm volatile("ldmatrix.sync.aligned.m8n8.x4.shared.b16 {%0,%1,%2,%3}, [%4];"
                 : "=r"(r[0]), "=r"(r[1]), "=r"(r[2]), "=r"(r[3]) : "r"(addr));
}
__device__ __forceinline__ void mma_f16(float (&d)[4], const uint32_t (&a)[4],
                                        uint32_t b0, uint32_t b1) {
    asm volatile(
        "mma.sync.aligned.m16n8k16.row.col.f32.f16.f16.f32 "
        "{%0,%1,%2,%3}, {%4,%5,%6,%7}, {%8,%9}, {%0,%1,%2,%3};"
        : "+f"(d[0]), "+f"(d[1]), "+f"(d[2]), "+f"(d[3])
        : "r"(a[0]), "r"(a[1]), "r"(a[2]), "r"(a[3]), "r"(b0), "r"(b1));
}
__device__ __forceinline__ float sigmoidf_(float x) { return 1.0f / (1.0f + expf(-x)); }
__device__ __forceinline__ float2 h2f(const __half* p) {
    return __half22float2(*(const __half2*)p);
}
// panel element offset for (row in 8192-row tensor, col in 512)
__device__ __forceinline__ size_t pidx(int row, int col) {
    return ((size_t)((row >> 7) * 8 + (col >> 6))) * PANEL_H + (row & 127) * 72 + (col & 63);
}

// ---------------- GEMM ------------------------------------------------------------
struct GemmArgs {
    const __half* A[3];         // panel bases, one per 512-wide K block
    const __half* Bt;           // weight panel base
    int kpb;                    // K panels per n-tile (K/64)
    const __half* P;            // row-major (pre-offset by step)
    const __half* C0;           // row-major
    const __half* x0;           // panel base
    const __half* xl;           // panel base (pre-offset by step)
    const float* bias0;
    const float* bias1;
    const float* hx;            // fp32 row-major
    const __half* U;            // row-major
    float* out0;                // fp32 row-major
    __half* out16a;
    __half* out16b;
};

#define MODE_PRE 0
#define MODE_C0  1
#define MODE_XI  2
#define MODE_UR  3
#define MODE_K   4

template <int MODE>
__device__ __forceinline__ void epi(const GemmArgs& g, int row, int col, float v0, float v1) {
    int c512 = col & 511;
    size_t idx = (size_t)row * Hdim + c512;
    if (MODE == MODE_PRE) {
        *(__half2*)(g.out16a + idx) = __floats2half2_rn(v0, v1);        // P row-major
    } else if (MODE == MODE_C0) {
        float2 b = *(const float2*)(g.bias0 + c512);
        *(__half2*)(g.out16a + idx) = __floats2half2_rn(v0 + b.x, v1 + b.y);
    } else if (MODE == MODE_XI) {
        size_t pp = pidx(row, c512);
        float2 p   = h2f(g.P  + idx);
        float2 c0v = h2f(g.C0 + idx);
        float2 x0v = h2f(g.x0 + pp);
        float2 xlv = h2f(g.xl + pp);
        float s0 = sigmoidf_(v0 + p.x + c0v.x);
        float s1 = sigmoidf_(v1 + p.y + c0v.y);
        *(__half2*)(g.out16a + pp) = __floats2half2_rn((1.f - s0) * x0v.x, (1.f - s1) * x0v.y);
        *(__half2*)(g.out16b + pp) = __floats2half2_rn(s0 * xlv.x, s1 * xlv.y);
    } else if (MODE == MODE_UR) {
        if (col < Hdim) {
            float2 b = *(const float2*)(g.bias0 + c512);
            *(__half2*)(g.out16a + idx) = __floats2half2_rn(sigmoidf_(v0 + b.x),
                                                            sigmoidf_(v1 + b.y));
        } else {
            float2 b = *(const float2*)(g.bias1 + c512);
            float2 h = *(const float2*)(g.hx + idx);
            *(__half2*)(g.out16b + pidx(row, c512)) =
                __floats2half2_rn(sigmoidf_(v0 + b.x) * h.x, sigmoidf_(v1 + b.y) * h.y);
        }
    } else { // MODE_K
        float2 b = *(const float2*)(g.bias0 + c512);
        float2 u = h2f(g.U + idx);
        float2 h = *(const float2*)(g.hx + idx);
        float k0 = tanhf(v0 + b.x), k1 = tanhf(v1 + b.y);
        float r0 = (1.f - u.x) * k0 + u.x * h.x;
        float r1 = (1.f - u.y) * k1 + u.y * h.y;
        *(float2*)(g.out0 + idx) = make_float2(r0, r1);
        *(__half2*)(g.out16a + pidx(row, c512)) = __floats2half2_rn(r0, r1);
    }
}

__device__ __forceinline__ void issue_bulk(const GemmArgs& g, int kb, int m_tile, int n_tile,
                                           uint32_t dst, uint32_t mbar) {
    MBARRIER_EXPECT_TX(mbar, STG_BYTES);
    const __half* srcA = g.A[kb >> 3] + ((size_t)m_tile * 8 + (kb & 7)) * PANEL_H;
    const __half* srcB = g.Bt + ((size_t)n_tile * g.kpb + kb) * PANEL_H;
    bulk_cp(dst, srcA, PANEL_BYTES, mbar);
    bulk_cp(dst + PANEL_BYTES, srcB, PANEL_BYTES, mbar);
}

// warp tile 64(M) x 32(N), BK=64
__device__ __forceinline__ void compute_stage(uint32_t base, uint32_t a_off, uint32_t b_off,
                                              float (&acc)[4][4][4]) {
#pragma unroll
    for (int kk = 0; kk < 4; ++kk) {
        uint32_t a[4][4];
        uint32_t b[2][4];
#pragma unroll
        for (int i = 0; i < 4; ++i)
            ldsm_x4(a[i], base + a_off + kk * 32 + i * (16 * 144));
#pragma unroll
        for (int jj = 0; jj < 2; ++jj)
            ldsm_x4(b[jj], base + b_off + kk * 32 + jj * (16 * 144));
#pragma unroll
        for (int i = 0; i < 4; ++i)
#pragma unroll
            for (int j = 0; j < 4; ++j)
                mma_f16(acc[i][j], a[i], b[j >> 1][(j & 1) * 2], b[j >> 1][(j & 1) * 2 + 1]);
    }
}

template <int MODE>
__global__ void __launch_bounds__(256, 2) gemm_bulk(GemmArgs args, int kblocks) {
    extern __shared__ char sm[];
    uint32_t su = smem_u32(sm);
    int tid = threadIdx.x;
    int warp = tid >> 5, lane = tid & 31;
    int MW = (warp & 1) * 64, NW = (warp >> 1) * 32;
    int g = lane >> 2, c = lane & 3;
    int m_tile = blockIdx.y, n_tile = blockIdx.x;
    int rowBase = m_tile * 128, colBase = n_tile * 128;

    if (tid == 0) {
        MBARRIER_INIT(su, 1);
        MBARRIER_INIT(su + 8, 1);
        MBARRIER_INIT(su + 16, 1);
    }
    __syncthreads();

    uint32_t a_off = (uint32_t)((MW + (lane & 15)) * 144 + (lane >> 4) * 16);
    uint32_t b_off = (uint32_t)(PANEL_BYTES + (NW + (lane & 7) + ((lane >> 4) << 3)) * 144
                                + ((lane >> 3) & 1) * 16);

    float acc[4][4][4];
#pragma unroll
    for (int i = 0; i < 4; ++i)
#pragma unroll
        for (int j = 0; j < 4; ++j)
#pragma unroll
            for (int e = 0; e < 4; ++e) acc[i][j][e] = 0.0f;

    if (tid == 0) {
#pragma unroll
        for (int s = 0; s < NSTAGE; ++s)
            issue_bulk(args, s, m_tile, n_tile, su + 64 + s * STG_BYTES, su + 8 * s);
    }

    int stage = 0;
    int par[NSTAGE] = {0, 0, 0};
    for (int kb = 0; kb < kblocks; ++kb) {
        MBARRIER_WAIT_PARITY(su + 8 * stage, par[stage]);
        par[stage] ^= 1;
        compute_stage(su + 64 + stage * STG_BYTES, a_off, b_off, acc);
        __syncthreads();           // all LDSM results consumed -> safe to refill
        if (tid == 0 && kb + NSTAGE < kblocks)
            issue_bulk(args, kb + NSTAGE, m_tile, n_tile,
                       su + 64 + stage * STG_BYTES, su + 8 * stage);
        stage = (stage + 1 == NSTAGE) ? 0 : stage + 1;
    }

    // epilogue
#pragma unroll
    for (int i = 0; i < 4; ++i) {
#pragma unroll
        for (int j = 0; j < 4; ++j) {
            int row = rowBase + MW + i * 16 + g;
            int col = colBase + NW + j * 8 + 2 * c;
            epi<MODE>(args, row, col, acc[i][j][0], acc[i][j][1]);
            epi<MODE>(args, row + 8, col, acc[i][j][2], acc[i][j][3]);
        }
    }
}

// ---------------- weight transpose into panels -----------------------------------
struct TransJobs {
    const float* src[7];
    __half* dst[7];
    int kpb[7];        // K panels of dst
    int nbase[7];      // n offset within dst
    int kbase[7];      // k offset within dst
    int ktiles[7];     // K/32 of src block
    int tileofs[7];
};

__global__ void transposeAll(TransJobs J) {
    __shared__ float t[32][33];
    int bid = blockIdx.x;
    int job = 0;
#pragma unroll
    for (int i = 1; i < 7; ++i)
        if (bid >= J.tileofs[i]) job = i;
    int local = bid - J.tileofs[job];
    int kt = J.ktiles[job];
    int kb = (local % kt) * 32;
    int nb = (local / kt) * 32;
    const float* src = J.src[job];
    __half* dst = J.dst[job];
    int KPB = J.kpb[job];
    int tx = threadIdx.x, ty = threadIdx.y;
#pragma unroll
    for (int i = 0; i < 32; i += 8)
        t[ty + i][tx] = src[(size_t)(kb + ty + i) * 512 + nb + tx];
    __syncthreads();
    int k = J.kbase[job] + kb + tx;
#pragma unroll
    for (int i = 0; i < 32; i += 8) {
        int n = J.nbase[job] + nb + ty + i;
        size_t off = ((size_t)((n >> 7) * KPB + (k >> 6))) * PANEL_H + (n & 127) * 72 + (k & 63);
        dst[off] = __float2half_rn(t[tx][ty + i]);
    }
}

// ---------------- fp32 -> fp16 convert into panels --------------------------------
__global__ void f2h_panel(const float* __restrict__ src, __half* __restrict__ dst, int n) {
    int i = (blockIdx.x * blockDim.x + threadIdx.x) * 8;
    if (i >= n) return;
    float4 v0 = *(const float4*)(src + i);
    float4 v1 = *(const float4*)(src + i + 4);
    __half2 h[4] = {__floats2half2_rn(v0.x, v0.y), __floats2half2_rn(v0.z, v0.w),
                    __floats2half2_rn(v1.x, v1.y), __floats2half2_rn(v1.z, v1.w)};
    int row = i >> 9, col = i & 511;
    size_t off = ((size_t)((row >> 7) * 8 + (col >> 6))) * PANEL_H + (row & 127) * 72 + (col & 63);
    *(uint4*)(dst + off) = *(uint4*)h;
}

// ---------------- host --------------------------------------------------------------
template <int MODE>
static void run_gemm(const GemmArgs& a, int mTiles, int nTiles, int kblocks) {
    cudaFuncSetAttribute(gemm_bulk<MODE>, cudaFuncAttributeMaxDynamicSharedMemorySize,
                         SMEM_BYTES);
    dim3 grid(nTiles, mTiles);
    gemm_bulk<MODE><<<grid, 256, SMEM_BYTES>>>(a, kblocks);
}

extern "C" void kernel_launch(void* const* d_in, const int* in_sizes, int n_in,
                              void* d_out, int out_size) {
    const float* edge = (const float*)d_in[0];
    const float* node = (const float*)d_in[1];
    const float* W_xi = (const float*)d_in[2];
    const float* b_xi = (const float*)d_in[3];
    const float* W_u  = (const float*)d_in[4];
    const float* b_u  = (const float*)d_in[5];
    const float* W_r  = (const float*)d_in[6];
    const float* b_r  = (const float*)d_in[7];
    const float* W_k  = (const float*)d_in[8];
    const float* b_k  = (const float*)d_in[9];
    float* hx = (float*)d_out;

    __half *P, *C0, *U;
    __half *E16, *N16, *X0H16, *XTH16, *RH16, *HX16, *W1T, *WpT, *W3T, *WurT, *WkT;
    cudaGetSymbolAddress((void**)&P,     g_P);
    cudaGetSymbolAddress((void**)&C0,    g_C0);
    cudaGetSymbolAddress((void**)&U,     g_U);
    cudaGetSymbolAddress((void**)&E16,   g_E16);
    cudaGetSymbolAddress((void**)&N16,   g_N16);
    cudaGetSymbolAddress((void**)&X0H16, g_X0H16);
    cudaGetSymbolAddress((void**)&XTH16, g_XTH16);
    cudaGetSymbolAddress((void**)&RH16,  g_RH16);
    cudaGetSymbolAddress((void**)&HX16,  g_HX16);
    cudaGetSymbolAddress((void**)&W1T,   g_W1T);
    cudaGetSymbolAddress((void**)&WpT,   g_WpT);
    cudaGetSymbolAddress((void**)&W3T,   g_W3T);
    cudaGetSymbolAddress((void**)&WurT,  g_WurT);
    cudaGetSymbolAddress((void**)&WkT,   g_WkT);

    cudaMemsetAsync(d_out, 0, (size_t)out_size * sizeof(float), 0);
    cudaMemsetAsync(HX16, 0, sizeof(g_HX16), 0);

    // fp32 -> fp16 panels for edge / node (incl. x0)
    {
        int nE = Lsteps * NH;
        int nN = (Lsteps + 1) * NH;
        f2h_panel<<<(nE / 8 + 255) / 256, 256>>>(edge, E16, nE);
        f2h_panel<<<(nN / 8 + 255) / 256, 256>>>(node, N16, nN);
    }

    // weight transpose -> fp16 panels
    {
        TransJobs J;
        const float* srcs[7] = {W_xi, W_xi + 512 * 512, W_xi + 1536 * 512,
                                W_xi + 1024 * 512, W_u, W_r, W_k};
        __half* dsts[7] = {W1T, WpT, WpT, W3T, WurT, WurT, WkT};
        int kpbs[7]  = {8, 16, 16, 8, 24, 24, 24};
        int nbases[7] = {0, 0, 0, 0, 0, 512, 0};
        int kbases[7] = {0, 0, 512, 0, 0, 0, 0};
        int kts[7] = {16, 16, 16, 16, 48, 48, 48};
        int ofs = 0;
        for (int i = 0; i < 7; ++i) {
            J.src[i] = srcs[i]; J.dst[i] = dsts[i]; J.kpb[i] = kpbs[i];
            J.nbase[i] = nbases[i]; J.kbase[i] = kbases[i];
            J.ktiles[i] = kts[i]; J.tileofs[i] = ofs;
            ofs += kts[i] * 16;
        }
        transposeAll<<<ofs, dim3(32, 8)>>>(J);
    }

    const __half* x016 = N16 + (size_t)1024 * 8 * PANEL_H;   // layer 16 panels

    // PRE: P[l] = el @ W2 + xl @ W4   (M = L*N, K = 1024) -> P row-major fp16
    {
        GemmArgs a = {};
        a.A[0] = E16; a.A[1] = N16;
        a.Bt = WpT; a.kpb = 16;
        a.out16a = P;
        run_gemm<MODE_PRE>(a, 1024, 4, 16);
    }
    // C0 = x0 @ W3 + b_xi
    {
        GemmArgs a = {};
        a.A[0] = x016;
        a.Bt = W3T; a.kpb = 8;
        a.bias0 = b_xi; a.out16a = C0;
        run_gemm<MODE_C0>(a, 64, 4, 8);
    }

    for (int l = 0; l < Lsteps; ++l) {
        // xi gate -> X0H, XTH panels
        {
            GemmArgs a = {};
            a.A[0] = HX16;
            a.Bt = W1T; a.kpb = 8;
            a.P = P + (size_t)l * NH; a.C0 = C0;
            a.x0 = x016; a.xl = N16 + (size_t)(l * 64) * 8 * PANEL_H;
            a.out16a = X0H16; a.out16b = XTH16;
            run_gemm<MODE_XI>(a, 64, 4, 8);
        }
        // fused u | r -> U (row-major), RH panels
        {
            GemmArgs a = {};
            a.A[0] = HX16; a.A[1] = X0H16; a.A[2] = XTH16;
            a.Bt = WurT; a.kpb = 24;
            a.bias0 = b_u; a.bias1 = b_r; a.hx = hx;
            a.out16a = U; a.out16b = RH16;
            run_gemm<MODE_UR>(a, 64, 8, 24);
        }
        // k + state update -> hx (fp32) + HX panels
        {
            GemmArgs a = {};
            a.A[0] = X0H16; a.A[1] = XTH16; a.A[2] = RH16;
            a.Bt = WkT; a.kpb = 24;
            a.bias0 = b_k; a.U = U; a.hx = hx;
            a.out0 = hx; a.out16a = HX16;
            run_gemm<MODE_K>(a, 64, 4, 24);
        }
    }
}

// round 10
// speedup vs baseline: 1.3417x; 1.1154x over previous
#include <cuda_runtime.h>
#include <cuda_fp16.h>
#include <math.h>
#include <stdint.h>

// Problem constants
#define Hdim 512
#define Lsteps 16
#define Nrows 8192
#define NH (Nrows * Hdim)

// Panel: 128 rows x 64 fp16, 144B pitch (16B pad) = exact smem stage layout
#define PANEL_H 9216                    // halves per panel
#define PANEL_BYTES 18432
#define STG_BYTES 36864                 // A panel + B panel
#define NSTAGE 3
#define SMEM_BYTES (64 + NSTAGE * STG_BYTES)   // 110656

// ---------------- scratch (device globals) ------------------------------------
__device__ __half g_P[Lsteps * (size_t)NH];     // row-major (epilogue operand)
__device__ __half g_C0[NH];                     // row-major
__device__ __half g_U[NH];                      // row-major
// panelized A-operand tensors
__device__ __half g_E16[75497472];              // 1024 tiles * 8 panels
__device__ __half g_N16[80216064];              // 1088 tiles * 8 panels (17 layers)
__device__ __half g_X0H16[4718592];             // 64 tiles * 8 panels
__device__ __half g_XTH16[4718592];
__device__ __half g_RH16[4718592];
__device__ __half g_HX16[4718592];
// panelized weights
__device__ __half g_W1T[294912];                // 4 ntiles * 8 kpanels
__device__ __half g_WpT[589824];                // 4 * 16
__device__ __half g_W3T[294912];                // 4 * 8
__device__ __half g_WurT[1769472];              // 8 * 24
__device__ __half g_WkT[884736];                // 4 * 24

// ---------------- helpers -------------------------------------------------------
__device__ __forceinline__ uint32_t smem_u32(const void* p) {
    uint32_t a;
    asm("{ .reg .u64 t; cvta.to.shared.u64 t, %1; cvt.u32.u64 %0, t; }" : "=r"(a) : "l"(p));
    return a;
}
#define MBARRIER_INIT(addr, cnt) \
    asm volatile("mbarrier.init.shared.b64 [%0], %1;" :: "r"((uint32_t)(addr)), "r"((uint32_t)(cnt)) : "memory")
#define MBARRIER_EXPECT_TX(addr, tx) \
    asm volatile("mbarrier.arrive.expect_tx.shared.b64 _, [%0], %1;" :: "r"((uint32_t)(addr)), "r"((uint32_t)(tx)) : "memory")
#define MBARRIER_ARRIVE(addr) \
    asm volatile("mbarrier.arrive.shared.b64 _, [%0];" :: "r"((uint32_t)(addr)) : "memory")
#define MBARRIER_WAIT_PARITY(addr, par) do { \
    uint32_t _m = (uint32_t)(addr); uint32_t _p = (uint32_t)(par); uint32_t _d; \
    asm volatile("{\n\t.reg .pred p;\n\t" \
        "mbarrier.try_wait.parity.acquire.cta.shared::cta.b64 p, [%1], %2;\n\t" \
        "selp.b32 %0, 1, 0, p;\n\t}" : "=r"(_d) : "r"(_m), "r"(_p) : "memory"); \
    if (!_d) { \
        asm volatile("{\n\t.reg .pred P1;\n\t" \
            "WL_%=:\n\t" \
            "mbarrier.try_wait.parity.acquire.cta.shared::cta.b64 P1, [%0], %1, 0x989680;\n\t" \
            "@P1 bra.uni WD_%=;\n\t" \
            "bra.uni WL_%=;\n\t" \
            "WD_%=:\n\t}" :: "r"(_m), "r"(_p) : "memory"); \
    } } while (0)

__device__ __forceinline__ void bulk_cp(uint32_t dst, const void* src, uint32_t bytes,
                                        uint32_t mbar) {
    asm volatile(
        "cp.async.bulk.shared::cluster.global.mbarrier::complete_tx::bytes "
        "[%0], [%1], %2, [%3];"
        :: "r"(dst), "l"(src), "r"(bytes), "r"(mbar) : "memory");
}

__device__ __forceinline__ void ldsm_x4(uint32_t (&r)[4], uint32_t addr) {
    asm volatile("ldmatrix.sync.aligned.m8n8.x4.shared.b16 {%0,%1,%2,%3}, [%4];"
                 : "=r"(r[0]), "=r"(r[1]), "=r"(r[2]), "=r"(r[3]) : "r"(addr));
}
__device__ __forceinline__ void mma_f16(float (&d)[4], const uint32_t (&a)[4],
                                        uint32_t b0, uint32_t b1) {
    asm volatile(
        "mma.sync.aligned.m16n8k16.row.col.f32.f16.f16.f32 "
        "{%0,%1,%2,%3}, {%4,%5,%6,%7}, {%8,%9}, {%0,%1,%2,%3};"
        : "+f"(d[0]), "+f"(d[1]), "+f"(d[2]), "+f"(d[3])
        : "r"(a[0]), "r"(a[1]), "r"(a[2]), "r"(a[3]), "r"(b0), "r"(b1));
}
__device__ __forceinline__ float sigmoidf_(float x) { return 1.0f / (1.0f + expf(-x)); }
__device__ __forceinline__ float2 h2f(const __half* p) {
    return __half22float2(*(const __half2*)p);
}
// panel element offset for (row in 8192-row tensor, col in 512)
__device__ __forceinline__ size_t pidx(int row, int col) {
    return ((size_t)((row >> 7) * 8 + (col >> 6))) * PANEL_H + (row & 127) * 72 + (col & 63);
}

// ---------------- GEMM ------------------------------------------------------------
struct GemmArgs {
    const __half* A[3];         // panel bases, one per 512-wide K block
    const __half* Bt;           // weight panel base
    int kpb;                    // K panels per n-tile (K/64)
    const __half* P;            // row-major (pre-offset by step)
    const __half* C0;           // row-major
    const __half* x0;           // panel base
    const __half* xl;           // panel base (pre-offset by step)
    const __half* hxp;          // hx panel base (fp16)
    const float* bias0;
    const float* bias1;
    const float* hx;            // fp32 row-major
    const __half* U;            // row-major
    float* out0;                // fp32 row-major
    __half* out16a;
    __half* out16b;
};

#define MODE_PRE 0
#define MODE_C0  1
#define MODE_XI  2
#define MODE_UR  3
#define MODE_K   4

template <int MODE>
__device__ __forceinline__ void epi(const GemmArgs& g, int row, int col, float v0, float v1) {
    int c512 = col & 511;
    size_t idx = (size_t)row * Hdim + c512;
    if (MODE == MODE_PRE) {
        *(__half2*)(g.out16a + idx) = __floats2half2_rn(v0, v1);        // P row-major
    } else if (MODE == MODE_C0) {
        float2 b = *(const float2*)(g.bias0 + c512);
        *(__half2*)(g.out16a + idx) = __floats2half2_rn(v0 + b.x, v1 + b.y);
    } else if (MODE == MODE_XI) {
        size_t pp = pidx(row, c512);
        float2 p   = h2f(g.P  + idx);
        float2 c0v = h2f(g.C0 + idx);
        float2 x0v = h2f(g.x0 + pp);
        float2 xlv = h2f(g.xl + pp);
        float s0 = sigmoidf_(v0 + p.x + c0v.x);
        float s1 = sigmoidf_(v1 + p.y + c0v.y);
        *(__half2*)(g.out16a + pp) = __floats2half2_rn((1.f - s0) * x0v.x, (1.f - s1) * x0v.y);
        *(__half2*)(g.out16b + pp) = __floats2half2_rn(s0 * xlv.x, s1 * xlv.y);
    } else if (MODE == MODE_UR) {
        if (col < Hdim) {
            float2 b = *(const float2*)(g.bias0 + c512);
            *(__half2*)(g.out16a + idx) = __floats2half2_rn(sigmoidf_(v0 + b.x),
                                                            sigmoidf_(v1 + b.y));
        } else {
            size_t pp = pidx(row, c512);
            float2 b = *(const float2*)(g.bias1 + c512);
            float2 h = h2f(g.hxp + pp);          // fp16 hx panels
            *(__half2*)(g.out16b + pp) =
                __floats2half2_rn(sigmoidf_(v0 + b.x) * h.x, sigmoidf_(v1 + b.y) * h.y);
        }
    } else { // MODE_K
        float2 b = *(const float2*)(g.bias0 + c512);
        float2 u = h2f(g.U + idx);
        float2 h = *(const float2*)(g.hx + idx);
        float k0 = tanhf(v0 + b.x), k1 = tanhf(v1 + b.y);
        float r0 = (1.f - u.x) * k0 + u.x * h.x;
        float r1 = (1.f - u.y) * k1 + u.y * h.y;
        *(float2*)(g.out0 + idx) = make_float2(r0, r1);
        *(__half2*)(g.out16a + pidx(row, c512)) = __floats2half2_rn(r0, r1);
    }
}

__device__ __forceinline__ void issue_bulk(const GemmArgs& g, int kb, int m_tile, int n_tile,
                                           uint32_t dst, uint32_t mbar) {
    MBARRIER_EXPECT_TX(mbar, STG_BYTES);
    const __half* srcA = g.A[kb >> 3] + ((size_t)m_tile * 8 + (kb & 7)) * PANEL_H;
    const __half* srcB = g.Bt + ((size_t)n_tile * g.kpb + kb) * PANEL_H;
    bulk_cp(dst, srcA, PANEL_BYTES, mbar);
    bulk_cp(dst + PANEL_BYTES, srcB, PANEL_BYTES, mbar);
}

// warp tile 64(M) x 32(N), BK=64
__device__ __forceinline__ void compute_stage(uint32_t base, uint32_t a_off, uint32_t b_off,
                                              float (&acc)[4][4][4]) {
#pragma unroll
    for (int kk = 0; kk < 4; ++kk) {
        uint32_t a[4][4];
        uint32_t b[2][4];
#pragma unroll
        for (int i = 0; i < 4; ++i)
            ldsm_x4(a[i], base + a_off + kk * 32 + i * (16 * 144));
#pragma unroll
        for (int jj = 0; jj < 2; ++jj)
            ldsm_x4(b[jj], base + b_off + kk * 32 + jj * (16 * 144));
#pragma unroll
        for (int i = 0; i < 4; ++i)
#pragma unroll
            for (int j = 0; j < 4; ++j)
                mma_f16(acc[i][j], a[i], b[j >> 1][(j & 1) * 2], b[j >> 1][(j & 1) * 2 + 1]);
    }
}

template <int MODE>
__global__ void __launch_bounds__(256, 2) gemm_bulk(GemmArgs args, int kblocks) {
    extern __shared__ char sm[];
    uint32_t su = smem_u32(sm);
    int tid = threadIdx.x;
    int warp = tid >> 5, lane = tid & 31;
    int MW = (warp & 1) * 64, NW = (warp >> 1) * 32;
    int g = lane >> 2, c = lane & 3;
    int m_tile = blockIdx.y, n_tile = blockIdx.x;
    int rowBase = m_tile * 128, colBase = n_tile * 128;

    // full barriers at su+0/8/16 (count 1, tx); empty barriers at su+24/32/40 (count 8)
    if (tid == 0) {
        MBARRIER_INIT(su + 0, 1);  MBARRIER_INIT(su + 8, 1);  MBARRIER_INIT(su + 16, 1);
        MBARRIER_INIT(su + 24, 8); MBARRIER_INIT(su + 32, 8); MBARRIER_INIT(su + 40, 8);
    }
    __syncthreads();

    uint32_t a_off = (uint32_t)((MW + (lane & 15)) * 144 + (lane >> 4) * 16);
    uint32_t b_off = (uint32_t)(PANEL_BYTES + (NW + (lane & 7) + ((lane >> 4) << 3)) * 144
                                + ((lane >> 3) & 1) * 16);

    float acc[4][4][4];
#pragma unroll
    for (int i = 0; i < 4; ++i)
#pragma unroll
        for (int j = 0; j < 4; ++j)
#pragma unroll
            for (int e = 0; e < 4; ++e) acc[i][j][e] = 0.0f;

    if (tid == 0) {
        int ni = kblocks < NSTAGE ? kblocks : NSTAGE;
        for (int s = 0; s < ni; ++s)
            issue_bulk(args, s, m_tile, n_tile, su + 64 + s * STG_BYTES, su + 8 * s);
    }

    int cs = 0, cp = 0;      // consumer cursor on full barriers
    int ps = 0, pp = 0;      // producer cursor on empty barriers (first reuse waits phase 0)
    for (int kb = 0; kb < kblocks; ++kb) {
        MBARRIER_WAIT_PARITY(su + 8 * cs, cp);
        compute_stage(su + 64 + cs * STG_BYTES, a_off, b_off, acc);
        if (lane == 0) MBARRIER_ARRIVE(su + 24 + 8 * cs);
        if (tid == 0 && kb + NSTAGE < kblocks) {
            MBARRIER_WAIT_PARITY(su + 24 + 8 * ps, pp);
            issue_bulk(args, kb + NSTAGE, m_tile, n_tile,
                       su + 64 + ps * STG_BYTES, su + 8 * ps);
            if (++ps == NSTAGE) { ps = 0; pp ^= 1; }
        }
        if (++cs == NSTAGE) { cs = 0; cp ^= 1; }
    }

    // epilogue
#pragma unroll
    for (int i = 0; i < 4; ++i) {
#pragma unroll
        for (int j = 0; j < 4; ++j) {
            int row = rowBase + MW + i * 16 + g;
            int col = colBase + NW + j * 8 + 2 * c;
            epi<MODE>(args, row, col, acc[i][j][0], acc[i][j][1]);
            epi<MODE>(args, row + 8, col, acc[i][j][2], acc[i][j][3]);
        }
    }
}

// ---------------- weight transpose into panels -----------------------------------
struct TransJobs {
    const float* src[7];
    __half* dst[7];
    int kpb[7];        // K panels of dst
    int nbase[7];      // n offset within dst
    int kbase[7];      // k offset within dst
    int ktiles[7];     // K/32 of src block
    int tileofs[7];
};

__global__ void transposeAll(TransJobs J) {
    __shared__ float t[32][33];
    int bid = blockIdx.x;
    int job = 0;
#pragma unroll
    for (int i = 1; i < 7; ++i)
        if (bid >= J.tileofs[i]) job = i;
    int local = bid - J.tileofs[job];
    int kt = J.ktiles[job];
    int kb = (local % kt) * 32;
    int nb = (local / kt) * 32;
    const float* src = J.src[job];
    __half* dst = J.dst[job];
    int KPB = J.kpb[job];
    int tx = threadIdx.x, ty = threadIdx.y;
#pragma unroll
    for (int i = 0; i < 32; i += 8)
        t[ty + i][tx] = src[(size_t)(kb + ty + i) * 512 + nb + tx];
    __syncthreads();
    int k = J.kbase[job] + kb + tx;
#pragma unroll
    for (int i = 0; i < 32; i += 8) {
        int n = J.nbase[job] + nb + ty + i;
        size_t off = ((size_t)((n >> 7) * KPB + (k >> 6))) * PANEL_H + (n & 127) * 72 + (k & 63);
        dst[off] = __float2half_rn(t[tx][ty + i]);
    }
}

// ---------------- fp32 -> fp16 convert into panels --------------------------------
__global__ void f2h_panel(const float* __restrict__ src, __half* __restrict__ dst, int n) {
    int i = (blockIdx.x * blockDim.x + threadIdx.x) * 8;
    if (i >= n) return;
    float4 v0 = *(const float4*)(src + i);
    float4 v1 = *(const float4*)(src + i + 4);
    __half2 h[4] = {__floats2half2_rn(v0.x, v0.y), __floats2half2_rn(v0.z, v0.w),
                    __floats2half2_rn(v1.x, v1.y), __floats2half2_rn(v1.z, v1.w)};
    int row = i >> 9, col = i & 511;
    size_t off = ((size_t)((row >> 7) * 8 + (col >> 6))) * PANEL_H + (row & 127) * 72 + (col & 63);
    *(uint4*)(dst + off) = *(uint4*)h;
}

// ---------------- host --------------------------------------------------------------
template <int MODE>
static void run_gemm(const GemmArgs& a, int mTiles, int nTiles, int kblocks) {
    cudaFuncSetAttribute(gemm_bulk<MODE>, cudaFuncAttributeMaxDynamicSharedMemorySize,
                         SMEM_BYTES);
    dim3 grid(nTiles, mTiles);
    gemm_bulk<MODE><<<grid, 256, SMEM_BYTES>>>(a, kblocks);
}

extern "C" void kernel_launch(void* const* d_in, const int* in_sizes, int n_in,
                              void* d_out, int out_size) {
    const float* edge = (const float*)d_in[0];
    const float* node = (const float*)d_in[1];
    const float* W_xi = (const float*)d_in[2];
    const float* b_xi = (const float*)d_in[3];
    const float* W_u  = (const float*)d_in[4];
    const float* b_u  = (const float*)d_in[5];
    const float* W_r  = (const float*)d_in[6];
    const float* b_r  = (const float*)d_in[7];
    const float* W_k  = (const float*)d_in[8];
    const float* b_k  = (const float*)d_in[9];
    float* hx = (float*)d_out;

    __half *P, *C0, *U;
    __half *E16, *N16, *X0H16, *XTH16, *RH16, *HX16, *W1T, *WpT, *W3T, *WurT, *WkT;
    cudaGetSymbolAddress((void**)&P,     g_P);
    cudaGetSymbolAddress((void**)&C0,    g_C0);
    cudaGetSymbolAddress((void**)&U,     g_U);
    cudaGetSymbolAddress((void**)&E16,   g_E16);
    cudaGetSymbolAddress((void**)&N16,   g_N16);
    cudaGetSymbolAddress((void**)&X0H16, g_X0H16);
    cudaGetSymbolAddress((void**)&XTH16, g_XTH16);
    cudaGetSymbolAddress((void**)&RH16,  g_RH16);
    cudaGetSymbolAddress((void**)&HX16,  g_HX16);
    cudaGetSymbolAddress((void**)&W1T,   g_W1T);
    cudaGetSymbolAddress((void**)&WpT,   g_WpT);
    cudaGetSymbolAddress((void**)&W3T,   g_W3T);
    cudaGetSymbolAddress((void**)&WurT,  g_WurT);
    cudaGetSymbolAddress((void**)&WkT,   g_WkT);

    cudaMemsetAsync(d_out, 0, (size_t)out_size * sizeof(float), 0);
    cudaMemsetAsync(HX16, 0, sizeof(g_HX16), 0);

    // fp32 -> fp16 panels for edge / node (incl. x0)
    {
        int nE = Lsteps * NH;
        int nN = (Lsteps + 1) * NH;
        f2h_panel<<<(nE / 8 + 255) / 256, 256>>>(edge, E16, nE);
        f2h_panel<<<(nN / 8 + 255) / 256, 256>>>(node, N16, nN);
    }

    // weight transpose -> fp16 panels
    {
        TransJobs J;
        const float* srcs[7] = {W_xi, W_xi + 512 * 512, W_xi + 1536 * 512,
                                W_xi + 1024 * 512, W_u, W_r, W_k};
        __half* dsts[7] = {W1T, WpT, WpT, W3T, WurT, WurT, WkT};
        int kpbs[7]  = {8, 16, 16, 8, 24, 24, 24};
        int nbases[7] = {0, 0, 0, 0, 0, 512, 0};
        int kbases[7] = {0, 0, 512, 0, 0, 0, 0};
        int kts[7] = {16, 16, 16, 16, 48, 48, 48};
        int ofs = 0;
        for (int i = 0; i < 7; ++i) {
            J.src[i] = srcs[i]; J.dst[i] = dsts[i]; J.kpb[i] = kpbs[i];
            J.nbase[i] = nbases[i]; J.kbase[i] = kbases[i];
            J.ktiles[i] = kts[i]; J.tileofs[i] = ofs;
            ofs += kts[i] * 16;
        }
        transposeAll<<<ofs, dim3(32, 8)>>>(J);
    }

    const __half* x016 = N16 + (size_t)1024 * 8 * PANEL_H;   // layer 16 panels

    // PRE: P[l] = el @ W2 + xl @ W4   (M = L*N, K = 1024) -> P row-major fp16
    {
        GemmArgs a = {};
        a.A[0] = E16; a.A[1] = N16;
        a.Bt = WpT; a.kpb = 16;
        a.out16a = P;
        run_gemm<MODE_PRE>(a, 1024, 4, 16);
    }
    // C0 = x0 @ W3 + b_xi
    {
        GemmArgs a = {};
        a.A[0] = x016;
        a.Bt = W3T; a.kpb = 8;
        a.bias0 = b_xi; a.out16a = C0;
        run_gemm<MODE_C0>(a, 64, 4, 8);
    }

    for (int l = 0; l < Lsteps; ++l) {
        // xi gate -> X0H, XTH panels
        {
            GemmArgs a = {};
            a.A[0] = HX16;
            a.Bt = W1T; a.kpb = 8;
            a.P = P + (size_t)l * NH; a.C0 = C0;
            a.x0 = x016; a.xl = N16 + (size_t)(l * 64) * 8 * PANEL_H;
            a.out16a = X0H16; a.out16b = XTH16;
            run_gemm<MODE_XI>(a, 64, 4, 8);
        }
        // fused u | r -> U (row-major), RH panels
        {
            GemmArgs a = {};
            a.A[0] = HX16; a.A[1] = X0H16; a.A[2] = XTH16;
            a.Bt = WurT; a.kpb = 24;
            a.bias0 = b_u; a.bias1 = b_r; a.hxp = HX16;
            a.out16a = U; a.out16b = RH16;
            run_gemm<MODE_UR>(a, 64, 8, 24);
        }
        // k + state update -> hx (fp32) + HX panels
        {
            GemmArgs a = {};
            a.A[0] = X0H16; a.A[1] = XTH16; a.A[2] = RH16;
            a.Bt = WkT; a.kpb = 24;
            a.bias0 = b_k; a.U = U; a.hx = hx;
            a.out0 = hx; a.out16a = HX16;
            run_gemm<MODE_K>(a, 64, 4, 24);
        }
    }
}

// round 11
// speedup vs baseline: 1.3581x; 1.0122x over previous
#include <cuda_runtime.h>
#include <cuda_fp16.h>
#include <math.h>
#include <stdint.h>

// Problem constants
#define Hdim 512
#define Lsteps 16
#define Nrows 8192
#define NH (Nrows * Hdim)

// Panel: 128 rows x 64 fp16, 144B pitch (16B pad) = exact smem stage layout
#define PANEL_H 9216                    // halves per panel
#define PANEL_BYTES 18432
#define STG_BYTES 36864                 // A panel + B panel
#define NSTAGE 3
#define SMEM_BYTES (64 + NSTAGE * STG_BYTES)   // 110656

// ---------------- scratch (device globals) ------------------------------------
__device__ __half g_P[Lsteps * (size_t)NH];     // row-major (epilogue operand)
__device__ __half g_C0[NH];                     // row-major
__device__ __half g_U[NH];                      // row-major
// panelized A-operand tensors
__device__ __half g_E16[75497472];              // 1024 tiles * 8 panels
__device__ __half g_N16[80216064];              // 1088 tiles * 8 panels (17 layers)
__device__ __half g_X0H16[4718592];             // 64 tiles * 8 panels
__device__ __half g_XTH16[4718592];
__device__ __half g_RH16[4718592];
__device__ __half g_HX16[4718592];
// panelized weights
__device__ __half g_W1T[294912];                // 4 ntiles * 8 kpanels
__device__ __half g_WpT[589824];                // 4 * 16
__device__ __half g_W3T[294912];                // 4 * 8
__device__ __half g_WurT[1769472];              // 8 * 24
__device__ __half g_WkT[884736];                // 4 * 24

// ---------------- helpers -------------------------------------------------------
__device__ __forceinline__ uint32_t smem_u32(const void* p) {
    uint32_t a;
    asm("{ .reg .u64 t; cvta.to.shared.u64 t, %1; cvt.u32.u64 %0, t; }" : "=r"(a) : "l"(p));
    return a;
}
#define MBARRIER_INIT(addr, cnt) \
    asm volatile("mbarrier.init.shared.b64 [%0], %1;" :: "r"((uint32_t)(addr)), "r"((uint32_t)(cnt)) : "memory")
#define MBARRIER_EXPECT_TX(addr, tx) \
    asm volatile("mbarrier.arrive.expect_tx.shared.b64 _, [%0], %1;" :: "r"((uint32_t)(addr)), "r"((uint32_t)(tx)) : "memory")
#define MBARRIER_ARRIVE(addr) \
    asm volatile("mbarrier.arrive.shared.b64 _, [%0];" :: "r"((uint32_t)(addr)) : "memory")
#define MBARRIER_WAIT_PARITY(addr, par) do { \
    uint32_t _m = (uint32_t)(addr); uint32_t _p = (uint32_t)(par); uint32_t _d; \
    asm volatile("{\n\t.reg .pred p;\n\t" \
        "mbarrier.try_wait.parity.acquire.cta.shared::cta.b64 p, [%1], %2;\n\t" \
        "selp.b32 %0, 1, 0, p;\n\t}" : "=r"(_d) : "r"(_m), "r"(_p) : "memory"); \
    if (!_d) { \
        asm volatile("{\n\t.reg .pred P1;\n\t" \
            "WL_%=:\n\t" \
            "mbarrier.try_wait.parity.acquire.cta.shared::cta.b64 P1, [%0], %1, 0x989680;\n\t" \
            "@P1 bra.uni WD_%=;\n\t" \
            "bra.uni WL_%=;\n\t" \
            "WD_%=:\n\t}" :: "r"(_m), "r"(_p) : "memory"); \
    } } while (0)

__device__ __forceinline__ void bulk_cp(uint32_t dst, const void* src, uint32_t bytes,
                                        uint32_t mbar) {
    asm volatile(
        "cp.async.bulk.shared::cluster.global.mbarrier::complete_tx::bytes "
        "[%0], [%1], %2, [%3];"
        :: "r"(dst), "l"(src), "r"(bytes), "r"(mbar) : "memory");
}

__device__ __forceinline__ void ldsm_x4(uint32_t (&r)[4], uint32_t addr) {
    asm volatile("ldmatrix.sync.aligned.m8n8.x4.shared.b16 {%0,%1,%2,%3}, [%4];"
                 : "=r"(r[0]), "=r"(r[1]), "=r"(r[2]), "=r"(r[3]) : "r"(addr));
}
__device__ __forceinline__ void mma_f16(float (&d)[4], const uint32_t (&a)[4],
                                        uint32_t b0, uint32_t b1) {
    asm volatile(
        "mma.sync.aligned.m16n8k16.row.col.f32.f16.f16.f32 "
        "{%0,%1,%2,%3}, {%4,%5,%6,%7}, {%8,%9}, {%0,%1,%2,%3};"
        : "+f"(d[0]), "+f"(d[1]), "+f"(d[2]), "+f"(d[3])
        : "r"(a[0]), "r"(a[1]), "r"(a[2]), "r"(a[3]), "r"(b0), "r"(b1));
}
__device__ __forceinline__ float sigmoidf_(float x) { return 1.0f / (1.0f + expf(-x)); }
__device__ __forceinline__ float2 h2f(const __half* p) {
    return __half22float2(*(const __half2*)p);
}
// panel element offset for (row in 8192-row tensor, col in 512)
__device__ __forceinline__ size_t pidx(int row, int col) {
    return ((size_t)((row >> 7) * 8 + (col >> 6))) * PANEL_H + (row & 127) * 72 + (col & 63);
}

// ---------------- GEMM ------------------------------------------------------------
struct GemmArgs {
    const __half* A[3];         // panel bases, one per 512-wide K block
    const __half* Bt;           // weight panel base
    int kpb;                    // K panels per n-tile in the B layout
    int kb0;                    // first B k-panel to use (skip leading blocks)
    const __half* P;            // row-major (pre-offset by step)
    const __half* C0;           // row-major
    const __half* x0;           // panel base
    const __half* xl;           // panel base (pre-offset by step)
    const __half* hxp;          // hx panel base (fp16)
    const float* bias0;
    const float* bias1;
    const float* hx;            // fp32 row-major
    const __half* U;            // row-major
    float* out0;                // fp32 row-major
    __half* out16a;
    __half* out16b;
};

#define MODE_PRE 0
#define MODE_C0  1
#define MODE_XI  2
#define MODE_UR  3
#define MODE_K   4

template <int MODE>
__device__ __forceinline__ void epi(const GemmArgs& g, int row, int col, float v0, float v1) {
    int c512 = col & 511;
    size_t idx = (size_t)row * Hdim + c512;
    if (MODE == MODE_PRE) {
        *(__half2*)(g.out16a + idx) = __floats2half2_rn(v0, v1);        // P row-major
    } else if (MODE == MODE_C0) {
        float2 b = *(const float2*)(g.bias0 + c512);
        *(__half2*)(g.out16a + idx) = __floats2half2_rn(v0 + b.x, v1 + b.y);
    } else if (MODE == MODE_XI) {
        size_t pp = pidx(row, c512);
        float2 p   = h2f(g.P  + idx);
        float2 c0v = h2f(g.C0 + idx);
        float2 x0v = h2f(g.x0 + pp);
        float2 xlv = h2f(g.xl + pp);
        float s0 = sigmoidf_(v0 + p.x + c0v.x);
        float s1 = sigmoidf_(v1 + p.y + c0v.y);
        *(__half2*)(g.out16a + pp) = __floats2half2_rn((1.f - s0) * x0v.x, (1.f - s1) * x0v.y);
        *(__half2*)(g.out16b + pp) = __floats2half2_rn(s0 * xlv.x, s1 * xlv.y);
    } else if (MODE == MODE_UR) {
        if (col < Hdim) {
            float2 b = *(const float2*)(g.bias0 + c512);
            *(__half2*)(g.out16a + idx) = __floats2half2_rn(sigmoidf_(v0 + b.x),
                                                            sigmoidf_(v1 + b.y));
        } else {
            size_t pp = pidx(row, c512);
            float2 b = *(const float2*)(g.bias1 + c512);
            float2 h = h2f(g.hxp + pp);          // fp16 hx panels
            *(__half2*)(g.out16b + pp) =
                __floats2half2_rn(sigmoidf_(v0 + b.x) * h.x, sigmoidf_(v1 + b.y) * h.y);
        }
    } else { // MODE_K
        float2 b = *(const float2*)(g.bias0 + c512);
        float2 u = h2f(g.U + idx);
        float2 h = *(const float2*)(g.hx + idx);
        float k0 = tanhf(v0 + b.x), k1 = tanhf(v1 + b.y);
        float r0 = (1.f - u.x) * k0 + u.x * h.x;
        float r1 = (1.f - u.y) * k1 + u.y * h.y;
        *(float2*)(g.out0 + idx) = make_float2(r0, r1);
        *(__half2*)(g.out16a + pidx(row, c512)) = __floats2half2_rn(r0, r1);
    }
}

__device__ __forceinline__ void issue_bulk(const GemmArgs& g, int kb, int m_tile, int n_tile,
                                           uint32_t dst, uint32_t mbar) {
    MBARRIER_EXPECT_TX(mbar, STG_BYTES);
    const __half* srcA = g.A[kb >> 3] + ((size_t)m_tile * 8 + (kb & 7)) * PANEL_H;
    const __half* srcB = g.Bt + ((size_t)n_tile * g.kpb + g.kb0 + kb) * PANEL_H;
    bulk_cp(dst, srcA, PANEL_BYTES, mbar);
    bulk_cp(dst + PANEL_BYTES, srcB, PANEL_BYTES, mbar);
}

// warp tile 64(M) x 32(N), BK=64
__device__ __forceinline__ void compute_stage(uint32_t base, uint32_t a_off, uint32_t b_off,
                                              float (&acc)[4][4][4]) {
#pragma unroll
    for (int kk = 0; kk < 4; ++kk) {
        uint32_t a[4][4];
        uint32_t b[2][4];
#pragma unroll
        for (int i = 0; i < 4; ++i)
            ldsm_x4(a[i], base + a_off + kk * 32 + i * (16 * 144));
#pragma unroll
        for (int jj = 0; jj < 2; ++jj)
            ldsm_x4(b[jj], base + b_off + kk * 32 + jj * (16 * 144));
#pragma unroll
        for (int i = 0; i < 4; ++i)
#pragma unroll
            for (int j = 0; j < 4; ++j)
                mma_f16(acc[i][j], a[i], b[j >> 1][(j & 1) * 2], b[j >> 1][(j & 1) * 2 + 1]);
    }
}

template <int MODE>
__global__ void __launch_bounds__(256, 2) gemm_bulk(GemmArgs args, int kblocks) {
    extern __shared__ char sm[];
    uint32_t su = smem_u32(sm);
    int tid = threadIdx.x;
    int warp = tid >> 5, lane = tid & 31;
    int MW = (warp & 1) * 64, NW = (warp >> 1) * 32;
    int g = lane >> 2, c = lane & 3;
    int m_tile = blockIdx.y, n_tile = blockIdx.x;
    int rowBase = m_tile * 128, colBase = n_tile * 128;

    // full barriers at su+0/8/16 (count 1, tx); empty barriers at su+24/32/40 (count 8)
    if (tid == 0) {
        MBARRIER_INIT(su + 0, 1);  MBARRIER_INIT(su + 8, 1);  MBARRIER_INIT(su + 16, 1);
        MBARRIER_INIT(su + 24, 8); MBARRIER_INIT(su + 32, 8); MBARRIER_INIT(su + 40, 8);
    }
    __syncthreads();

    uint32_t a_off = (uint32_t)((MW + (lane & 15)) * 144 + (lane >> 4) * 16);
    uint32_t b_off = (uint32_t)(PANEL_BYTES + (NW + (lane & 7) + ((lane >> 4) << 3)) * 144
                                + ((lane >> 3) & 1) * 16);

    float acc[4][4][4];
#pragma unroll
    for (int i = 0; i < 4; ++i)
#pragma unroll
        for (int j = 0; j < 4; ++j)
#pragma unroll
            for (int e = 0; e < 4; ++e) acc[i][j][e] = 0.0f;

    if (tid == 0) {
        int ni = kblocks < NSTAGE ? kblocks : NSTAGE;
        for (int s = 0; s < ni; ++s)
            issue_bulk(args, s, m_tile, n_tile, su + 64 + s * STG_BYTES, su + 8 * s);
    }

    int cs = 0, cp = 0;      // consumer cursor on full barriers
    int ps = 0, pp = 0;      // producer cursor on empty barriers
    for (int kb = 0; kb < kblocks; ++kb) {
        MBARRIER_WAIT_PARITY(su + 8 * cs, cp);
        compute_stage(su + 64 + cs * STG_BYTES, a_off, b_off, acc);
        if (lane == 0) MBARRIER_ARRIVE(su + 24 + 8 * cs);
        // lagged producer: at kb refill for kb+2 into stage (kb-1)%3,
        // waiting on arrivals completed during iteration kb-1 (one-kb slack).
        if (tid == 0 && kb >= 1 && kb + 2 < kblocks) {
            MBARRIER_WAIT_PARITY(su + 24 + 8 * ps, pp);
            issue_bulk(args, kb + 2, m_tile, n_tile,
                       su + 64 + ps * STG_BYTES, su + 8 * ps);
            if (++ps == NSTAGE) { ps = 0; pp ^= 1; }
        }
        if (++cs == NSTAGE) { cs = 0; cp ^= 1; }
    }

    // epilogue
#pragma unroll
    for (int i = 0; i < 4; ++i) {
#pragma unroll
        for (int j = 0; j < 4; ++j) {
            int row = rowBase + MW + i * 16 + g;
            int col = colBase + NW + j * 8 + 2 * c;
            epi<MODE>(args, row, col, acc[i][j][0], acc[i][j][1]);
            epi<MODE>(args, row + 8, col, acc[i][j][2], acc[i][j][3]);
        }
    }
}

// ---------------- step-0 XI elementwise (hx0 == 0 -> no GEMM) ---------------------
__global__ void xi0_kernel(const __half* __restrict__ P0, const __half* __restrict__ C0,
                           const __half* __restrict__ x0p, const __half* __restrict__ xlp,
                           __half* __restrict__ X0H, __half* __restrict__ XTH) {
    int i = (blockIdx.x * blockDim.x + threadIdx.x) * 8;
    int row = i >> 9, col = i & 511;
    size_t pp = pidx(row, col);
    size_t idx = (size_t)row * Hdim + col;
    uint4 pv = *(const uint4*)(P0 + idx);
    uint4 cv = *(const uint4*)(C0 + idx);
    uint4 xv = *(const uint4*)(x0p + pp);
    uint4 lv = *(const uint4*)(xlp + pp);
    const __half2* ph = (const __half2*)&pv;
    const __half2* ch = (const __half2*)&cv;
    const __half2* xh = (const __half2*)&xv;
    const __half2* lh = (const __half2*)&lv;
    uint4 o0, o1;
    __half2* o0h = (__half2*)&o0;
    __half2* o1h = (__half2*)&o1;
#pragma unroll
    for (int q = 0; q < 4; ++q) {
        float2 p = __half22float2(ph[q]);
        float2 c = __half22float2(ch[q]);
        float2 x = __half22float2(xh[q]);
        float2 l = __half22float2(lh[q]);
        float s0 = sigmoidf_(p.x + c.x);
        float s1 = sigmoidf_(p.y + c.y);
        o0h[q] = __floats2half2_rn((1.f - s0) * x.x, (1.f - s1) * x.y);
        o1h[q] = __floats2half2_rn(s0 * l.x, s1 * l.y);
    }
    *(uint4*)(X0H + pp) = o0;
    *(uint4*)(XTH + pp) = o1;
}

// ---------------- weight transpose into panels -----------------------------------
struct TransJobs {
    const float* src[7];
    __half* dst[7];
    int kpb[7];        // K panels of dst
    int nbase[7];      // n offset within dst
    int kbase[7];      // k offset within dst
    int ktiles[7];     // K/32 of src block
    int tileofs[7];
};

__global__ void transposeAll(TransJobs J) {
    __shared__ float t[32][33];
    int bid = blockIdx.x;
    int job = 0;
#pragma unroll
    for (int i = 1; i < 7; ++i)
        if (bid >= J.tileofs[i]) job = i;
    int local = bid - J.tileofs[job];
    int kt = J.ktiles[job];
    int kb = (local % kt) * 32;
    int nb = (local / kt) * 32;
    const float* src = J.src[job];
    __half* dst = J.dst[job];
    int KPB = J.kpb[job];
    int tx = threadIdx.x, ty = threadIdx.y;
#pragma unroll
    for (int i = 0; i < 32; i += 8)
        t[ty + i][tx] = src[(size_t)(kb + ty + i) * 512 + nb + tx];
    __syncthreads();
    int k = J.kbase[job] + kb + tx;
#pragma unroll
    for (int i = 0; i < 32; i += 8) {
        int n = J.nbase[job] + nb + ty + i;
        size_t off = ((size_t)((n >> 7) * KPB + (k >> 6))) * PANEL_H + (n & 127) * 72 + (k & 63);
        dst[off] = __float2half_rn(t[tx][ty + i]);
    }
}

// ---------------- fp32 -> fp16 convert into panels --------------------------------
__global__ void f2h_panel(const float* __restrict__ src, __half* __restrict__ dst, int n) {
    int i = (blockIdx.x * blockDim.x + threadIdx.x) * 8;
    if (i >= n) return;
    float4 v0 = *(const float4*)(src + i);
    float4 v1 = *(const float4*)(src + i + 4);
    __half2 h[4] = {__floats2half2_rn(v0.x, v0.y), __floats2half2_rn(v0.z, v0.w),
                    __floats2half2_rn(v1.x, v1.y), __floats2half2_rn(v1.z, v1.w)};
    int row = i >> 9, col = i & 511;
    size_t off = ((size_t)((row >> 7) * 8 + (col >> 6))) * PANEL_H + (row & 127) * 72 + (col & 63);
    *(uint4*)(dst + off) = *(uint4*)h;
}

// ---------------- host --------------------------------------------------------------
template <int MODE>
static void run_gemm(const GemmArgs& a, int mTiles, int nTiles, int kblocks) {
    cudaFuncSetAttribute(gemm_bulk<MODE>, cudaFuncAttributeMaxDynamicSharedMemorySize,
                         SMEM_BYTES);
    dim3 grid(nTiles, mTiles);
    gemm_bulk<MODE><<<grid, 256, SMEM_BYTES>>>(a, kblocks);
}

extern "C" void kernel_launch(void* const* d_in, const int* in_sizes, int n_in,
                              void* d_out, int out_size) {
    const float* edge = (const float*)d_in[0];
    const float* node = (const float*)d_in[1];
    const float* W_xi = (const float*)d_in[2];
    const float* b_xi = (const float*)d_in[3];
    const float* W_u  = (const float*)d_in[4];
    const float* b_u  = (const float*)d_in[5];
    const float* W_r  = (const float*)d_in[6];
    const float* b_r  = (const float*)d_in[7];
    const float* W_k  = (const float*)d_in[8];
    const float* b_k  = (const float*)d_in[9];
    float* hx = (float*)d_out;

    __half *P, *C0, *U;
    __half *E16, *N16, *X0H16, *XTH16, *RH16, *HX16, *W1T, *WpT, *W3T, *WurT, *WkT;
    cudaGetSymbolAddress((void**)&P,     g_P);
    cudaGetSymbolAddress((void**)&C0,    g_C0);
    cudaGetSymbolAddress((void**)&U,     g_U);
    cudaGetSymbolAddress((void**)&E16,   g_E16);
    cudaGetSymbolAddress((void**)&N16,   g_N16);
    cudaGetSymbolAddress((void**)&X0H16, g_X0H16);
    cudaGetSymbolAddress((void**)&XTH16, g_XTH16);
    cudaGetSymbolAddress((void**)&RH16,  g_RH16);
    cudaGetSymbolAddress((void**)&HX16,  g_HX16);
    cudaGetSymbolAddress((void**)&W1T,   g_W1T);
    cudaGetSymbolAddress((void**)&WpT,   g_WpT);
    cudaGetSymbolAddress((void**)&W3T,   g_W3T);
    cudaGetSymbolAddress((void**)&WurT,  g_WurT);
    cudaGetSymbolAddress((void**)&WkT,   g_WkT);

    cudaMemsetAsync(d_out, 0, (size_t)out_size * sizeof(float), 0);
    cudaMemsetAsync(HX16, 0, sizeof(g_HX16), 0);

    // fp32 -> fp16 panels for edge / node (incl. x0)
    {
        int nE = Lsteps * NH;
        int nN = (Lsteps + 1) * NH;
        f2h_panel<<<(nE / 8 + 255) / 256, 256>>>(edge, E16, nE);
        f2h_panel<<<(nN / 8 + 255) / 256, 256>>>(node, N16, nN);
    }

    // weight transpose -> fp16 panels
    {
        TransJobs J;
        const float* srcs[7] = {W_xi, W_xi + 512 * 512, W_xi + 1536 * 512,
                                W_xi + 1024 * 512, W_u, W_r, W_k};
        __half* dsts[7] = {W1T, WpT, WpT, W3T, WurT, WurT, WkT};
        int kpbs[7]  = {8, 16, 16, 8, 24, 24, 24};
        int nbases[7] = {0, 0, 0, 0, 0, 512, 0};
        int kbases[7] = {0, 0, 512, 0, 0, 0, 0};
        int kts[7] = {16, 16, 16, 16, 48, 48, 48};
        int ofs = 0;
        for (int i = 0; i < 7; ++i) {
            J.src[i] = srcs[i]; J.dst[i] = dsts[i]; J.kpb[i] = kpbs[i];
            J.nbase[i] = nbases[i]; J.kbase[i] = kbases[i];
            J.ktiles[i] = kts[i]; J.tileofs[i] = ofs;
            ofs += kts[i] * 16;
        }
        transposeAll<<<ofs, dim3(32, 8)>>>(J);
    }

    const __half* x016 = N16 + (size_t)1024 * 8 * PANEL_H;   // layer 16 panels

    // PRE: P[l] = el @ W2 + xl @ W4   (M = L*N, K = 1024) -> P row-major fp16
    {
        GemmArgs a = {};
        a.A[0] = E16; a.A[1] = N16;
        a.Bt = WpT; a.kpb = 16;
        a.out16a = P;
        run_gemm<MODE_PRE>(a, 1024, 4, 16);
    }
    // C0 = x0 @ W3 + b_xi
    {
        GemmArgs a = {};
        a.A[0] = x016;
        a.Bt = W3T; a.kpb = 8;
        a.bias0 = b_xi; a.out16a = C0;
        run_gemm<MODE_C0>(a, 64, 4, 8);
    }

    for (int l = 0; l < Lsteps; ++l) {
        // xi gate -> X0H, XTH panels
        if (l == 0) {
            // hx0 == 0: the hx@W1 GEMM contributes exactly 0 -> pure elementwise
            xi0_kernel<<<NH / 8 / 256, 256>>>(P, C0, x016, N16, X0H16, XTH16);
        } else {
            GemmArgs a = {};
            a.A[0] = HX16;
            a.Bt = W1T; a.kpb = 8;
            a.P = P + (size_t)l * NH; a.C0 = C0;
            a.x0 = x016; a.xl = N16 + (size_t)(l * 64) * 8 * PANEL_H;
            a.out16a = X0H16; a.out16b = XTH16;
            run_gemm<MODE_XI>(a, 64, 4, 8);
        }
        // fused u | r -> U (row-major), RH panels
        {
            GemmArgs a = {};
            if (l == 0) {
                // hx block is zero: skip its K panels (B offset kb0 = 8)
                a.A[0] = X0H16; a.A[1] = XTH16;
                a.kb0 = 8;
                a.Bt = WurT; a.kpb = 24;
                a.bias0 = b_u; a.bias1 = b_r; a.hxp = HX16;
                a.out16a = U; a.out16b = RH16;
                run_gemm<MODE_UR>(a, 64, 8, 16);
            } else {
                a.A[0] = HX16; a.A[1] = X0H16; a.A[2] = XTH16;
                a.Bt = WurT; a.kpb = 24;
                a.bias0 = b_u; a.bias1 = b_r; a.hxp = HX16;
                a.out16a = U; a.out16b = RH16;
                run_gemm<MODE_UR>(a, 64, 8, 24);
            }
        }
        // k + state update -> hx (fp32) + HX panels
        {
            GemmArgs a = {};
            a.A[0] = X0H16; a.A[1] = XTH16; a.A[2] = RH16;
            a.Bt = WkT; a.kpb = 24;
            a.bias0 = b_k; a.U = U; a.hx = hx;
            a.out0 = hx; a.out16a = HX16;
            // l == 0: RH == 0 -> skip its K block (panels 16..23 of WkT)
            run_gemm<MODE_K>(a, 64, 4, l == 0 ? 16 : 24);
        }
    }
}

// round 12
// speedup vs baseline: 1.3614x; 1.0025x over previous
#include <cuda_runtime.h>
#include <cuda_fp16.h>
#include <math.h>
#include <stdint.h>

// Problem constants
#define Hdim 512
#define Lsteps 16
#define Nrows 8192
#define NH (Nrows * Hdim)

// Panel: 128 rows x 64 fp16, 144B pitch (16B pad) = exact smem stage layout
#define PANEL_H 9216                    // halves per panel
#define PANEL_BYTES 18432
#define STG_BYTES 36864                 // A panel + B panel
#define NSTAGE 3
#define SMEM_BYTES (64 + NSTAGE * STG_BYTES)   // 110656

// ---------------- scratch (device globals) ------------------------------------
__device__ __half g_P[Lsteps * (size_t)NH];     // row-major, includes +C0 (epilogue operand)
__device__ __half g_C0[NH];                     // row-major (x0@W3 + b_xi)
__device__ __half g_U[NH];                      // row-major
// panelized A-operand tensors
__device__ __half g_E16[75497472];              // 1024 tiles * 8 panels
__device__ __half g_N16[80216064];              // 1088 tiles * 8 panels (17 layers)
__device__ __half g_X0H16[4718592];             // 64 tiles * 8 panels
__device__ __half g_XTH16[4718592];
__device__ __half g_RH16[4718592];
__device__ __half g_HX16[4718592];              // fp16 recurrent state (panels)
// panelized weights
__device__ __half g_W1T[294912];                // 4 ntiles * 8 kpanels
__device__ __half g_WpT[589824];                // 4 * 16
__device__ __half g_W3T[294912];                // 4 * 8
__device__ __half g_WurT[1769472];              // 8 * 24
__device__ __half g_WkT[884736];                // 4 * 24

// ---------------- helpers -------------------------------------------------------
__device__ __forceinline__ uint32_t smem_u32(const void* p) {
    uint32_t a;
    asm("{ .reg .u64 t; cvta.to.shared.u64 t, %1; cvt.u32.u64 %0, t; }" : "=r"(a) : "l"(p));
    return a;
}
#define MBARRIER_INIT(addr, cnt) \
    asm volatile("mbarrier.init.shared.b64 [%0], %1;" :: "r"((uint32_t)(addr)), "r"((uint32_t)(cnt)) : "memory")
#define MBARRIER_EXPECT_TX(addr, tx) \
    asm volatile("mbarrier.arrive.expect_tx.shared.b64 _, [%0], %1;" :: "r"((uint32_t)(addr)), "r"((uint32_t)(tx)) : "memory")
#define MBARRIER_ARRIVE(addr) \
    asm volatile("mbarrier.arrive.shared.b64 _, [%0];" :: "r"((uint32_t)(addr)) : "memory")
#define MBARRIER_WAIT_PARITY(addr, par) do { \
    uint32_t _m = (uint32_t)(addr); uint32_t _p = (uint32_t)(par); uint32_t _d; \
    asm volatile("{\n\t.reg .pred p;\n\t" \
        "mbarrier.try_wait.parity.acquire.cta.shared::cta.b64 p, [%1], %2;\n\t" \
        "selp.b32 %0, 1, 0, p;\n\t}" : "=r"(_d) : "r"(_m), "r"(_p) : "memory"); \
    if (!_d) { \
        asm volatile("{\n\t.reg .pred P1;\n\t" \
            "WL_%=:\n\t" \
            "mbarrier.try_wait.parity.acquire.cta.shared::cta.b64 P1, [%0], %1, 0x989680;\n\t" \
            "@P1 bra.uni WD_%=;\n\t" \
            "bra.uni WL_%=;\n\t" \
            "WD_%=:\n\t}" :: "r"(_m), "r"(_p) : "memory"); \
    } } while (0)

__device__ __forceinline__ void bulk_cp(uint32_t dst, const void* src, uint32_t bytes,
                                        uint32_t mbar) {
    asm volatile(
        "cp.async.bulk.shared::cluster.global.mbarrier::complete_tx::bytes "
        "[%0], [%1], %2, [%3];"
        :: "r"(dst), "l"(src), "r"(bytes), "r"(mbar) : "memory");
}

__device__ __forceinline__ void ldsm_x4(uint32_t (&r)[4], uint32_t addr) {
    asm volatile("ldmatrix.sync.aligned.m8n8.x4.shared.b16 {%0,%1,%2,%3}, [%4];"
                 : "=r"(r[0]), "=r"(r[1]), "=r"(r[2]), "=r"(r[3]) : "r"(addr));
}
__device__ __forceinline__ void mma_f16(float (&d)[4], const uint32_t (&a)[4],
                                        uint32_t b0, uint32_t b1) {
    asm volatile(
        "mma.sync.aligned.m16n8k16.row.col.f32.f16.f16.f32 "
        "{%0,%1,%2,%3}, {%4,%5,%6,%7}, {%8,%9}, {%0,%1,%2,%3};"
        : "+f"(d[0]), "+f"(d[1]), "+f"(d[2]), "+f"(d[3])
        : "r"(a[0]), "r"(a[1]), "r"(a[2]), "r"(a[3]), "r"(b0), "r"(b1));
}
__device__ __forceinline__ float sigmoidf_(float x) { return 1.0f / (1.0f + expf(-x)); }
__device__ __forceinline__ float2 h2f(const __half* p) {
    return __half22float2(*(const __half2*)p);
}
// panel element offset for (row in 8192-row tensor, col in 512)
__device__ __forceinline__ size_t pidx(int row, int col) {
    return ((size_t)((row >> 7) * 8 + (col >> 6))) * PANEL_H + (row & 127) * 72 + (col & 63);
}

// ---------------- GEMM ------------------------------------------------------------
struct GemmArgs {
    const __half* A[3];         // panel bases, one per 512-wide K block
    const __half* Bt;           // weight panel base
    int kpb;                    // K panels per n-tile in the B layout
    int kb0;                    // first B k-panel to use (skip leading blocks)
    const __half* P;            // row-major (pre-offset by step; includes C0)
    const __half* C0;           // row-major (PRE folds this into P)
    const __half* x0;           // panel base
    const __half* xl;           // panel base (pre-offset by step)
    const __half* hxp;          // hx panel base (fp16 state)
    const float* bias0;
    const float* bias1;
    const __half* U;            // row-major
    float* out0;                // fp32 row-major (final step only; may be null)
    __half* out16a;
    __half* out16b;
};

#define MODE_PRE 0
#define MODE_C0  1
#define MODE_XI  2
#define MODE_UR  3
#define MODE_K   4

template <int MODE>
__device__ __forceinline__ void epi(const GemmArgs& g, int row, int col, float v0, float v1) {
    int c512 = col & 511;
    size_t idx = (size_t)row * Hdim + c512;
    if (MODE == MODE_PRE) {
        // fold C0 (indexed by n = row mod 8192) into P
        float2 c0v = h2f(g.C0 + (size_t)(row & (Nrows - 1)) * Hdim + c512);
        *(__half2*)(g.out16a + idx) = __floats2half2_rn(v0 + c0v.x, v1 + c0v.y);
    } else if (MODE == MODE_C0) {
        float2 b = *(const float2*)(g.bias0 + c512);
        *(__half2*)(g.out16a + idx) = __floats2half2_rn(v0 + b.x, v1 + b.y);
    } else if (MODE == MODE_XI) {
        size_t pp = pidx(row, c512);
        float2 p   = h2f(g.P  + idx);          // already includes C0
        float2 x0v = h2f(g.x0 + pp);
        float2 xlv = h2f(g.xl + pp);
        float s0 = sigmoidf_(v0 + p.x);
        float s1 = sigmoidf_(v1 + p.y);
        *(__half2*)(g.out16a + pp) = __floats2half2_rn((1.f - s0) * x0v.x, (1.f - s1) * x0v.y);
        *(__half2*)(g.out16b + pp) = __floats2half2_rn(s0 * xlv.x, s1 * xlv.y);
    } else if (MODE == MODE_UR) {
        if (col < Hdim) {
            float2 b = *(const float2*)(g.bias0 + c512);
            *(__half2*)(g.out16a + idx) = __floats2half2_rn(sigmoidf_(v0 + b.x),
                                                            sigmoidf_(v1 + b.y));
        } else {
            size_t pp = pidx(row, c512);
            float2 b = *(const float2*)(g.bias1 + c512);
            float2 h = h2f(g.hxp + pp);          // fp16 hx panels
            *(__half2*)(g.out16b + pp) =
                __floats2half2_rn(sigmoidf_(v0 + b.x) * h.x, sigmoidf_(v1 + b.y) * h.y);
        }
    } else { // MODE_K
        size_t pp = pidx(row, c512);
        float2 b = *(const float2*)(g.bias0 + c512);
        float2 u = h2f(g.U + idx);
        float2 h = h2f(g.hxp + pp);              // fp16 carried state
        float k0 = tanhf(v0 + b.x), k1 = tanhf(v1 + b.y);
        float r0 = (1.f - u.x) * k0 + u.x * h.x;
        float r1 = (1.f - u.y) * k1 + u.y * h.y;
        *(__half2*)(g.out16a + pp) = __floats2half2_rn(r0, r1);
        if (g.out0)                               // final step: fp32 output
            *(float2*)(g.out0 + idx) = make_float2(r0, r1);
    }
}

__device__ __forceinline__ void issue_bulk(const GemmArgs& g, int kb, int m_tile, int n_tile,
                                           uint32_t dst, uint32_t mbar) {
    MBARRIER_EXPECT_TX(mbar, STG_BYTES);
    const __half* srcA = g.A[kb >> 3] + ((size_t)m_tile * 8 + (kb & 7)) * PANEL_H;
    const __half* srcB = g.Bt + ((size_t)n_tile * g.kpb + g.kb0 + kb) * PANEL_H;
    bulk_cp(dst, srcA, PANEL_BYTES, mbar);
    bulk_cp(dst + PANEL_BYTES, srcB, PANEL_BYTES, mbar);
}

// warp tile 64(M) x 32(N), BK=64
__device__ __forceinline__ void compute_stage(uint32_t base, uint32_t a_off, uint32_t b_off,
                                              float (&acc)[4][4][4]) {
#pragma unroll
    for (int kk = 0; kk < 4; ++kk) {
        uint32_t a[4][4];
        uint32_t b[2][4];
#pragma unroll
        for (int i = 0; i < 4; ++i)
            ldsm_x4(a[i], base + a_off + kk * 32 + i * (16 * 144));
#pragma unroll
        for (int jj = 0; jj < 2; ++jj)
            ldsm_x4(b[jj], base + b_off + kk * 32 + jj * (16 * 144));
#pragma unroll
        for (int i = 0; i < 4; ++i)
#pragma unroll
            for (int j = 0; j < 4; ++j)
                mma_f16(acc[i][j], a[i], b[j >> 1][(j & 1) * 2], b[j >> 1][(j & 1) * 2 + 1]);
    }
}

template <int MODE>
__global__ void __launch_bounds__(256, 2) gemm_bulk(GemmArgs args, int kblocks) {
    extern __shared__ char sm[];
    uint32_t su = smem_u32(sm);
    int tid = threadIdx.x;
    int warp = tid >> 5, lane = tid & 31;
    int MW = (warp & 1) * 64, NW = (warp >> 1) * 32;
    int g = lane >> 2, c = lane & 3;
    int m_tile = blockIdx.y, n_tile = blockIdx.x;
    int rowBase = m_tile * 128, colBase = n_tile * 128;

    // full barriers at su+0/8/16 (count 1, tx); empty barriers at su+24/32/40 (count 8)
    if (tid == 0) {
        MBARRIER_INIT(su + 0, 1);  MBARRIER_INIT(su + 8, 1);  MBARRIER_INIT(su + 16, 1);
        MBARRIER_INIT(su + 24, 8); MBARRIER_INIT(su + 32, 8); MBARRIER_INIT(su + 40, 8);
    }
    __syncthreads();

    uint32_t a_off = (uint32_t)((MW + (lane & 15)) * 144 + (lane >> 4) * 16);
    uint32_t b_off = (uint32_t)(PANEL_BYTES + (NW + (lane & 7) + ((lane >> 4) << 3)) * 144
                                + ((lane >> 3) & 1) * 16);

    float acc[4][4][4];
#pragma unroll
    for (int i = 0; i < 4; ++i)
#pragma unroll
        for (int j = 0; j < 4; ++j)
#pragma unroll
            for (int e = 0; e < 4; ++e) acc[i][j][e] = 0.0f;

    if (tid == 0) {
        int ni = kblocks < NSTAGE ? kblocks : NSTAGE;
        for (int s = 0; s < ni; ++s)
            issue_bulk(args, s, m_tile, n_tile, su + 64 + s * STG_BYTES, su + 8 * s);
    }

    int cs = 0, cp = 0;      // consumer cursor on full barriers
    int ps = 0, pp = 0;      // producer cursor on empty barriers
    for (int kb = 0; kb < kblocks; ++kb) {
        MBARRIER_WAIT_PARITY(su + 8 * cs, cp);
        compute_stage(su + 64 + cs * STG_BYTES, a_off, b_off, acc);
        if (lane == 0) MBARRIER_ARRIVE(su + 24 + 8 * cs);
        if (tid == 0 && kb + NSTAGE < kblocks) {
            MBARRIER_WAIT_PARITY(su + 24 + 8 * ps, pp);
            issue_bulk(args, kb + NSTAGE, m_tile, n_tile,
                       su + 64 + ps * STG_BYTES, su + 8 * ps);
            if (++ps == NSTAGE) { ps = 0; pp ^= 1; }
        }
        if (++cs == NSTAGE) { cs = 0; cp ^= 1; }
    }

    // epilogue
#pragma unroll
    for (int i = 0; i < 4; ++i) {
#pragma unroll
        for (int j = 0; j < 4; ++j) {
            int row = rowBase + MW + i * 16 + g;
            int col = colBase + NW + j * 8 + 2 * c;
            epi<MODE>(args, row, col, acc[i][j][0], acc[i][j][1]);
            epi<MODE>(args, row + 8, col, acc[i][j][2], acc[i][j][3]);
        }
    }
}

// ---------------- step-0 XI elementwise (hx0 == 0 -> no GEMM) ---------------------
__global__ void xi0_kernel(const __half* __restrict__ P0,
                           const __half* __restrict__ x0p, const __half* __restrict__ xlp,
                           __half* __restrict__ X0H, __half* __restrict__ XTH) {
    int i = (blockIdx.x * blockDim.x + threadIdx.x) * 8;
    int row = i >> 9, col = i & 511;
    size_t pp = pidx(row, col);
    size_t idx = (size_t)row * Hdim + col;
    uint4 pv = *(const uint4*)(P0 + idx);       // P already includes C0
    uint4 xv = *(const uint4*)(x0p + pp);
    uint4 lv = *(const uint4*)(xlp + pp);
    const __half2* ph = (const __half2*)&pv;
    const __half2* xh = (const __half2*)&xv;
    const __half2* lh = (const __half2*)&lv;
    uint4 o0, o1;
    __half2* o0h = (__half2*)&o0;
    __half2* o1h = (__half2*)&o1;
#pragma unroll
    for (int q = 0; q < 4; ++q) {
        float2 p = __half22float2(ph[q]);
        float2 x = __half22float2(xh[q]);
        float2 l = __half22float2(lh[q]);
        float s0 = sigmoidf_(p.x);
        float s1 = sigmoidf_(p.y);
        o0h[q] = __floats2half2_rn((1.f - s0) * x.x, (1.f - s1) * x.y);
        o1h[q] = __floats2half2_rn(s0 * l.x, s1 * l.y);
    }
    *(uint4*)(X0H + pp) = o0;
    *(uint4*)(XTH + pp) = o1;
}

// ---------------- weight transpose into panels -----------------------------------
struct TransJobs {
    const float* src[7];
    __half* dst[7];
    int kpb[7];        // K panels of dst
    int nbase[7];      // n offset within dst
    int kbase[7];      // k offset within dst
    int ktiles[7];     // K/32 of src block
    int tileofs[7];
};

__global__ void transposeAll(TransJobs J) {
    __shared__ float t[32][33];
    int bid = blockIdx.x;
    int job = 0;
#pragma unroll
    for (int i = 1; i < 7; ++i)
        if (bid >= J.tileofs[i]) job = i;
    int local = bid - J.tileofs[job];
    int kt = J.ktiles[job];
    int kb = (local % kt) * 32;
    int nb = (local / kt) * 32;
    const float* src = J.src[job];
    __half* dst = J.dst[job];
    int KPB = J.kpb[job];
    int tx = threadIdx.x, ty = threadIdx.y;
#pragma unroll
    for (int i = 0; i < 32; i += 8)
        t[ty + i][tx] = src[(size_t)(kb + ty + i) * 512 + nb + tx];
    __syncthreads();
    int k = J.kbase[job] + kb + tx;
#pragma unroll
    for (int i = 0; i < 32; i += 8) {
        int n = J.nbase[job] + nb + ty + i;
        size_t off = ((size_t)((n >> 7) * KPB + (k >> 6))) * PANEL_H + (n & 127) * 72 + (k & 63);
        dst[off] = __float2half_rn(t[tx][ty + i]);
    }
}

// ---------------- fp32 -> fp16 convert into panels --------------------------------
__global__ void f2h_panel(const float* __restrict__ src, __half* __restrict__ dst, int n) {
    int i = (blockIdx.x * blockDim.x + threadIdx.x) * 8;
    if (i >= n) return;
    float4 v0 = *(const float4*)(src + i);
    float4 v1 = *(const float4*)(src + i + 4);
    __half2 h[4] = {__floats2half2_rn(v0.x, v0.y), __floats2half2_rn(v0.z, v0.w),
                    __floats2half2_rn(v1.x, v1.y), __floats2half2_rn(v1.z, v1.w)};
    int row = i >> 9, col = i & 511;
    size_t off = ((size_t)((row >> 7) * 8 + (col >> 6))) * PANEL_H + (row & 127) * 72 + (col & 63);
    *(uint4*)(dst + off) = *(uint4*)h;
}

// ---------------- host --------------------------------------------------------------
template <int MODE>
static void run_gemm(const GemmArgs& a, int mTiles, int nTiles, int kblocks) {
    cudaFuncSetAttribute(gemm_bulk<MODE>, cudaFuncAttributeMaxDynamicSharedMemorySize,
                         SMEM_BYTES);
    dim3 grid(nTiles, mTiles);
    gemm_bulk<MODE><<<grid, 256, SMEM_BYTES>>>(a, kblocks);
}

extern "C" void kernel_launch(void* const* d_in, const int* in_sizes, int n_in,
                              void* d_out, int out_size) {
    const float* edge = (const float*)d_in[0];
    const float* node = (const float*)d_in[1];
    const float* W_xi = (const float*)d_in[2];
    const float* b_xi = (const float*)d_in[3];
    const float* W_u  = (const float*)d_in[4];
    const float* b_u  = (const float*)d_in[5];
    const float* W_r  = (const float*)d_in[6];
    const float* b_r  = (const float*)d_in[7];
    const float* W_k  = (const float*)d_in[8];
    const float* b_k  = (const float*)d_in[9];
    float* hx = (float*)d_out;

    __half *P, *C0, *U;
    __half *E16, *N16, *X0H16, *XTH16, *RH16, *HX16, *W1T, *WpT, *W3T, *WurT, *WkT;
    cudaGetSymbolAddress((void**)&P,     g_P);
    cudaGetSymbolAddress((void**)&C0,    g_C0);
    cudaGetSymbolAddress((void**)&U,     g_U);
    cudaGetSymbolAddress((void**)&E16,   g_E16);
    cudaGetSymbolAddress((void**)&N16,   g_N16);
    cudaGetSymbolAddress((void**)&X0H16, g_X0H16);
    cudaGetSymbolAddress((void**)&XTH16, g_XTH16);
    cudaGetSymbolAddress((void**)&RH16,  g_RH16);
    cudaGetSymbolAddress((void**)&HX16,  g_HX16);
    cudaGetSymbolAddress((void**)&W1T,   g_W1T);
    cudaGetSymbolAddress((void**)&WpT,   g_WpT);
    cudaGetSymbolAddress((void**)&W3T,   g_W3T);
    cudaGetSymbolAddress((void**)&WurT,  g_WurT);
    cudaGetSymbolAddress((void**)&WkT,   g_WkT);

    cudaMemsetAsync(HX16, 0, sizeof(g_HX16), 0);

    // fp32 -> fp16 panels for edge / node (incl. x0)
    {
        int nE = Lsteps * NH;
        int nN = (Lsteps + 1) * NH;
        f2h_panel<<<(nE / 8 + 255) / 256, 256>>>(edge, E16, nE);
        f2h_panel<<<(nN / 8 + 255) / 256, 256>>>(node, N16, nN);
    }

    // weight transpose -> fp16 panels
    {
        TransJobs J;
        const float* srcs[7] = {W_xi, W_xi + 512 * 512, W_xi + 1536 * 512,
                                W_xi + 1024 * 512, W_u, W_r, W_k};
        __half* dsts[7] = {W1T, WpT, WpT, W3T, WurT, WurT, WkT};
        int kpbs[7]  = {8, 16, 16, 8, 24, 24, 24};
        int nbases[7] = {0, 0, 0, 0, 0, 512, 0};
        int kbases[7] = {0, 0, 512, 0, 0, 0, 0};
        int kts[7] = {16, 16, 16, 16, 48, 48, 48};
        int ofs = 0;
        for (int i = 0; i < 7; ++i) {
            J.src[i] = srcs[i]; J.dst[i] = dsts[i]; J.kpb[i] = kpbs[i];
            J.nbase[i] = nbases[i]; J.kbase[i] = kbases[i];
            J.ktiles[i] = kts[i]; J.tileofs[i] = ofs;
            ofs += kts[i] * 16;
        }
        transposeAll<<<ofs, dim3(32, 8)>>>(J);
    }

    const __half* x016 = N16 + (size_t)1024 * 8 * PANEL_H;   // layer 16 panels

    // C0 = x0 @ W3 + b_xi  (must precede PRE, which folds C0 into P)
    {
        GemmArgs a = {};
        a.A[0] = x016;
        a.Bt = W3T; a.kpb = 8;
        a.bias0 = b_xi; a.out16a = C0;
        run_gemm<MODE_C0>(a, 64, 4, 8);
    }
    // PRE: P[l] = el @ W2 + xl @ W4 + C0   (M = L*N, K = 1024) -> P row-major fp16
    {
        GemmArgs a = {};
        a.A[0] = E16; a.A[1] = N16;
        a.Bt = WpT; a.kpb = 16;
        a.C0 = C0;
        a.out16a = P;
        run_gemm<MODE_PRE>(a, 1024, 4, 16);
    }

    for (int l = 0; l < Lsteps; ++l) {
        // xi gate -> X0H, XTH panels
        if (l == 0) {
            // hx0 == 0: the hx@W1 GEMM contributes exactly 0 -> pure elementwise
            xi0_kernel<<<NH / 8 / 256, 256>>>(P, x016, N16, X0H16, XTH16);
        } else {
            GemmArgs a = {};
            a.A[0] = HX16;
            a.Bt = W1T; a.kpb = 8;
            a.P = P + (size_t)l * NH;
            a.x0 = x016; a.xl = N16 + (size_t)(l * 64) * 8 * PANEL_H;
            a.out16a = X0H16; a.out16b = XTH16;
            run_gemm<MODE_XI>(a, 64, 4, 8);
        }
        // fused u | r -> U (row-major), RH panels
        {
            GemmArgs a = {};
            if (l == 0) {
                a.A[0] = X0H16; a.A[1] = XTH16;
                a.kb0 = 8;
                a.Bt = WurT; a.kpb = 24;
                a.bias0 = b_u; a.bias1 = b_r; a.hxp = HX16;
                a.out16a = U; a.out16b = RH16;
                run_gemm<MODE_UR>(a, 64, 8, 16);
            } else {
                a.A[0] = HX16; a.A[1] = X0H16; a.A[2] = XTH16;
                a.Bt = WurT; a.kpb = 24;
                a.bias0 = b_u; a.bias1 = b_r; a.hxp = HX16;
                a.out16a = U; a.out16b = RH16;
                run_gemm<MODE_UR>(a, 64, 8, 24);
            }
        }
        // k + state update -> HX16 (fp16 state), + fp32 d_out on final step
        {
            GemmArgs a = {};
            a.A[0] = X0H16; a.A[1] = XTH16; a.A[2] = RH16;
            a.Bt = WkT; a.kpb = 24;
            a.bias0 = b_k; a.U = U; a.hxp = HX16;
            a.out16a = HX16;
            a.out0 = (l == Lsteps - 1) ? hx : nullptr;
            run_gemm<MODE_K>(a, 64, 4, l == 0 ? 16 : 24);
        }
    }
}

// round 13
// speedup vs baseline: 1.3615x; 1.0001x over previous
#include <cuda_runtime.h>
#include <cuda_fp16.h>
#include <math.h>
#include <stdint.h>

// Problem constants
#define Hdim 512
#define Lsteps 16
#define Nrows 8192
#define NH (Nrows * Hdim)

// Panel: 128 rows x 64 fp16, 144B pitch (16B pad) = exact smem stage layout
#define PANEL_H 9216                    // halves per panel
#define PANEL_BYTES 18432
#define STG_BYTES 36864                 // A panel + B panel
#define NSTAGE 3
#define SMEM_BYTES (64 + NSTAGE * STG_BYTES)   // 110656

// ---------------- scratch (device globals) ------------------------------------
__device__ __half g_P[Lsteps * (size_t)NH];     // row-major, includes +C0
__device__ __half g_C0[NH];                     // row-major (x0@W3 + b_xi)
__device__ __half g_U[NH];                      // row-major
__device__ __half g_E16[75497472];              // panels
__device__ __half g_N16[80216064];              // panels (17 layers)
__device__ __half g_X0H16[4718592];
__device__ __half g_XTH16[4718592];
__device__ __half g_RH16[4718592];
__device__ __half g_HX16[4718592];              // fp16 recurrent state (panels)
__device__ __half g_W1T[294912];
__device__ __half g_WpT[589824];
__device__ __half g_W3T[294912];
__device__ __half g_WurT[1769472];
__device__ __half g_WkT[884736];
// group barrier state (64 groups)
__device__ unsigned g_grpCnt[64];
__device__ unsigned g_grpGen[64];

// ---------------- helpers -------------------------------------------------------
__device__ __forceinline__ uint32_t smem_u32(const void* p) {
    uint32_t a;
    asm("{ .reg .u64 t; cvta.to.shared.u64 t, %1; cvt.u32.u64 %0, t; }" : "=r"(a) : "l"(p));
    return a;
}
#define MBARRIER_INIT(addr, cnt) \
    asm volatile("mbarrier.init.shared.b64 [%0], %1;" :: "r"((uint32_t)(addr)), "r"((uint32_t)(cnt)) : "memory")
#define MBARRIER_EXPECT_TX(addr, tx) \
    asm volatile("mbarrier.arrive.expect_tx.shared.b64 _, [%0], %1;" :: "r"((uint32_t)(addr)), "r"((uint32_t)(tx)) : "memory")
#define MBARRIER_ARRIVE(addr) \
    asm volatile("mbarrier.arrive.shared.b64 _, [%0];" :: "r"((uint32_t)(addr)) : "memory")
#define MBARRIER_WAIT_PARITY(addr, par) do { \
    uint32_t _m = (uint32_t)(addr); uint32_t _p = (uint32_t)(par); uint32_t _d; \
    asm volatile("{\n\t.reg .pred p;\n\t" \
        "mbarrier.try_wait.parity.acquire.cta.shared::cta.b64 p, [%1], %2;\n\t" \
        "selp.b32 %0, 1, 0, p;\n\t}" : "=r"(_d) : "r"(_m), "r"(_p) : "memory"); \
    if (!_d) { \
        asm volatile("{\n\t.reg .pred P1;\n\t" \
            "WL_%=:\n\t" \
            "mbarrier.try_wait.parity.acquire.cta.shared::cta.b64 P1, [%0], %1, 0x989680;\n\t" \
            "@P1 bra.uni WD_%=;\n\t" \
            "bra.uni WL_%=;\n\t" \
            "WD_%=:\n\t}" :: "r"(_m), "r"(_p) : "memory"); \
    } } while (0)

__device__ __forceinline__ void bulk_cp(uint32_t dst, const void* src, uint32_t bytes,
                                        uint32_t mbar) {
    asm volatile(
        "cp.async.bulk.shared::cluster.global.mbarrier::complete_tx::bytes "
        "[%0], [%1], %2, [%3];"
        :: "r"(dst), "l"(src), "r"(bytes), "r"(mbar) : "memory");
}

__device__ __forceinline__ void ldsm_x4(uint32_t (&r)[4], uint32_t addr) {
    asm volatile("ldmatrix.sync.aligned.m8n8.x4.shared.b16 {%0,%1,%2,%3}, [%4];"
                 : "=r"(r[0]), "=r"(r[1]), "=r"(r[2]), "=r"(r[3]) : "r"(addr));
}
__device__ __forceinline__ void mma_f16(float (&d)[4], const uint32_t (&a)[4],
                                        uint32_t b0, uint32_t b1) {
    asm volatile(
        "mma.sync.aligned.m16n8k16.row.col.f32.f16.f16.f32 "
        "{%0,%1,%2,%3}, {%4,%5,%6,%7}, {%8,%9}, {%0,%1,%2,%3};"
        : "+f"(d[0]), "+f"(d[1]), "+f"(d[2]), "+f"(d[3])
        : "r"(a[0]), "r"(a[1]), "r"(a[2]), "r"(a[3]), "r"(b0), "r"(b1));
}
__device__ __forceinline__ float sigmoidf_(float x) { return 1.0f / (1.0f + expf(-x)); }
__device__ __forceinline__ float2 h2f(const __half* p) {
    return __half22float2(*(const __half2*)p);
}
__device__ __forceinline__ size_t pidx(int row, int col) {
    return ((size_t)((row >> 7) * 8 + (col >> 6))) * PANEL_H + (row & 127) * 72 + (col & 63);
}

// group barrier: 4 CTAs per group, sense-reversing
__device__ __forceinline__ void group_barrier(int grp, int tid) {
    __syncthreads();
    if (tid == 0) {
        __threadfence();
        unsigned gen = ((volatile unsigned*)g_grpGen)[grp];
        if (atomicAdd(&g_grpCnt[grp], 1u) == 3u) {
            g_grpCnt[grp] = 0;
            __threadfence();
            atomicAdd(&g_grpGen[grp], 1u);
        } else {
            while (((volatile unsigned*)g_grpGen)[grp] == gen)
                asm volatile("nanosleep.u32 64;");
        }
        __threadfence();
        asm volatile("fence.proxy.async;" ::: "memory");
    }
    __syncthreads();
}

// ---------------- GEMM ------------------------------------------------------------
struct GemmArgs {
    const __half* A[3];
    const __half* Bt;
    int kpb;
    int kb0;
    const __half* P;
    const __half* C0;
    const __half* x0;
    const __half* xl;
    const __half* hxp;
    const float* bias0;
    const float* bias1;
    const __half* U;
    float* out0;
    __half* out16a;
    __half* out16b;
};

#define MODE_PRE 0
#define MODE_C0  1
#define MODE_XI  2
#define MODE_UR  3
#define MODE_K   4

template <int MODE>
__device__ __forceinline__ void epi(const GemmArgs& g, int row, int col, float v0, float v1) {
    int c512 = col & 511;
    size_t idx = (size_t)row * Hdim + c512;
    if (MODE == MODE_PRE) {
        float2 c0v = h2f(g.C0 + (size_t)(row & (Nrows - 1)) * Hdim + c512);
        *(__half2*)(g.out16a + idx) = __floats2half2_rn(v0 + c0v.x, v1 + c0v.y);
    } else if (MODE == MODE_C0) {
        float2 b = *(const float2*)(g.bias0 + c512);
        *(__half2*)(g.out16a + idx) = __floats2half2_rn(v0 + b.x, v1 + b.y);
    } else if (MODE == MODE_XI) {
        size_t pp = pidx(row, c512);
        float2 p   = h2f(g.P  + idx);
        float2 x0v = h2f(g.x0 + pp);
        float2 xlv = h2f(g.xl + pp);
        float s0 = sigmoidf_(v0 + p.x);
        float s1 = sigmoidf_(v1 + p.y);
        *(__half2*)(g.out16a + pp) = __floats2half2_rn((1.f - s0) * x0v.x, (1.f - s1) * x0v.y);
        *(__half2*)(g.out16b + pp) = __floats2half2_rn(s0 * xlv.x, s1 * xlv.y);
    } else if (MODE == MODE_UR) {
        if (col < Hdim) {
            float2 b = *(const float2*)(g.bias0 + c512);
            *(__half2*)(g.out16a + idx) = __floats2half2_rn(sigmoidf_(v0 + b.x),
                                                            sigmoidf_(v1 + b.y));
        } else {
            size_t pp = pidx(row, c512);
            float2 b = *(const float2*)(g.bias1 + c512);
            float2 h = h2f(g.hxp + pp);
            *(__half2*)(g.out16b + pp) =
                __floats2half2_rn(sigmoidf_(v0 + b.x) * h.x, sigmoidf_(v1 + b.y) * h.y);
        }
    } else { // MODE_K
        size_t pp = pidx(row, c512);
        float2 b = *(const float2*)(g.bias0 + c512);
        float2 u = h2f(g.U + idx);
        float2 h = h2f(g.hxp + pp);
        float k0 = tanhf(v0 + b.x), k1 = tanhf(v1 + b.y);
        float r0 = (1.f - u.x) * k0 + u.x * h.x;
        float r1 = (1.f - u.y) * k1 + u.y * h.y;
        *(__half2*)(g.out16a + pp) = __floats2half2_rn(r0, r1);
        if (g.out0)
            *(float2*)(g.out0 + idx) = make_float2(r0, r1);
    }
}

__device__ __forceinline__ void issue_chunk(const GemmArgs& g, int kb, int m_tile, int n_tile,
                                            uint32_t dst, uint32_t mbar) {
    MBARRIER_EXPECT_TX(mbar, STG_BYTES);
    const __half* srcA = g.A[kb >> 3] + ((size_t)m_tile * 8 + (kb & 7)) * PANEL_H;
    const __half* srcB = g.Bt + ((size_t)n_tile * g.kpb + g.kb0 + kb) * PANEL_H;
    bulk_cp(dst, srcA, PANEL_BYTES, mbar);
    bulk_cp(dst + PANEL_BYTES, srcB, PANEL_BYTES, mbar);
}

__device__ __forceinline__ void compute_stage(uint32_t base, uint32_t a_off, uint32_t b_off,
                                              float (&acc)[4][4][4]) {
#pragma unroll
    for (int kk = 0; kk < 4; ++kk) {
        uint32_t a[4][4];
        uint32_t b[2][4];
#pragma unroll
        for (int i = 0; i < 4; ++i)
            ldsm_x4(a[i], base + a_off + kk * 32 + i * (16 * 144));
#pragma unroll
        for (int jj = 0; jj < 2; ++jj)
            ldsm_x4(b[jj], base + b_off + kk * 32 + jj * (16 * 144));
#pragma unroll
        for (int i = 0; i < 4; ++i)
#pragma unroll
            for (int j = 0; j < 4; ++j)
                mma_f16(acc[i][j], a[i], b[j >> 1][(j & 1) * 2], b[j >> 1][(j & 1) * 2 + 1]);
    }
}

// ------------- standalone GEMM kernel (PRE / C0 / fallback) ------------------------
template <int MODE>
__global__ void __launch_bounds__(256, 2) gemm_bulk(GemmArgs args, int kblocks) {
    extern __shared__ char sm[];
    uint32_t su = smem_u32(sm);
    int tid = threadIdx.x;
    int warp = tid >> 5, lane = tid & 31;
    int MW = (warp & 1) * 64, NW = (warp >> 1) * 32;
    int g = lane >> 2, c = lane & 3;
    int m_tile = blockIdx.y, n_tile = blockIdx.x;
    int rowBase = m_tile * 128, colBase = n_tile * 128;

    if (tid == 0) {
        MBARRIER_INIT(su + 0, 1);  MBARRIER_INIT(su + 8, 1);  MBARRIER_INIT(su + 16, 1);
        MBARRIER_INIT(su + 24, 8); MBARRIER_INIT(su + 32, 8); MBARRIER_INIT(su + 40, 8);
    }
    __syncthreads();

    uint32_t a_off = (uint32_t)((MW + (lane & 15)) * 144 + (lane >> 4) * 16);
    uint32_t b_off = (uint32_t)(PANEL_BYTES + (NW + (lane & 7) + ((lane >> 4) << 3)) * 144
                                + ((lane >> 3) & 1) * 16);

    float acc[4][4][4];
#pragma unroll
    for (int i = 0; i < 4; ++i)
#pragma unroll
        for (int j = 0; j < 4; ++j)
#pragma unroll
            for (int e = 0; e < 4; ++e) acc[i][j][e] = 0.0f;

    if (tid == 0) {
        int ni = kblocks < NSTAGE ? kblocks : NSTAGE;
        for (int s = 0; s < ni; ++s)
            issue_chunk(args, s, m_tile, n_tile, su + 64 + s * STG_BYTES, su + 8 * s);
    }

    int cs = 0, cp = 0;
    int ps = 0, pp = 0;
    for (int kb = 0; kb < kblocks; ++kb) {
        MBARRIER_WAIT_PARITY(su + 8 * cs, cp);
        compute_stage(su + 64 + cs * STG_BYTES, a_off, b_off, acc);
        if (lane == 0) MBARRIER_ARRIVE(su + 24 + 8 * cs);
        if (tid == 0 && kb + NSTAGE < kblocks) {
            MBARRIER_WAIT_PARITY(su + 24 + 8 * ps, pp);
            issue_chunk(args, kb + NSTAGE, m_tile, n_tile,
                        su + 64 + ps * STG_BYTES, su + 8 * ps);
            if (++ps == NSTAGE) { ps = 0; pp ^= 1; }
        }
        if (++cs == NSTAGE) { cs = 0; cp ^= 1; }
    }

#pragma unroll
    for (int i = 0; i < 4; ++i) {
#pragma unroll
        for (int j = 0; j < 4; ++j) {
            int row = rowBase + MW + i * 16 + g;
            int col = colBase + NW + j * 8 + 2 * c;
            epi<MODE>(args, row, col, acc[i][j][0], acc[i][j][1]);
            epi<MODE>(args, row + 8, col, acc[i][j][2], acc[i][j][3]);
        }
    }
}

// ------------- persistent recurrence -----------------------------------------------
struct Pipe { int cs, cp, ps, pp; };

template <int MODE>
__device__ __forceinline__ void run_phase(const GemmArgs& args, int kblocks, int T,
                                          int n0, int nstep, int m_tile, Pipe& P,
                                          uint32_t su, uint32_t a_off, uint32_t b_off,
                                          int lane, int MW, int NW, int g, int c) {
    int tid = threadIdx.x;
    int rowBase = m_tile * 128;
    int total = T * kblocks;

    float acc[4][4][4];
#pragma unroll
    for (int i = 0; i < 4; ++i)
#pragma unroll
        for (int j = 0; j < 4; ++j)
#pragma unroll
            for (int e = 0; e < 4; ++e) acc[i][j][e] = 0.0f;

    for (int i = 0; i < total; ++i) {
        if (tid == 0) {
            int lo = (i == 0) ? 0 : i + 2;
            int hi = i + 2;
            for (int j = lo; j <= hi; ++j) {
                if (j >= total) break;
                MBARRIER_WAIT_PARITY(su + 24 + 8 * P.ps, P.pp);
                int tj = j / kblocks;
                int kb = j - tj * kblocks;
                issue_chunk(args, kb, m_tile, n0 + nstep * tj,
                            su + 64 + P.ps * STG_BYTES, su + 8 * P.ps);
                if (++P.ps == NSTAGE) { P.ps = 0; P.pp ^= 1; }
            }
        } else {
            // keep cursor state consistent in all threads
            int lo = (i == 0) ? 0 : i + 2;
            for (int j = lo; j <= i + 2 && j < total; ++j)
                if (++P.ps == NSTAGE) { P.ps = 0; P.pp ^= 1; }
        }
        MBARRIER_WAIT_PARITY(su + 8 * P.cs, P.cp);
        compute_stage(su + 64 + P.cs * STG_BYTES, a_off, b_off, acc);
        if (lane == 0) MBARRIER_ARRIVE(su + 24 + 8 * P.cs);
        if (++P.cs == NSTAGE) { P.cs = 0; P.cp ^= 1; }

        if (((i + 1) % kblocks) == 0) {
            int tt = i / kblocks;
            int colBase = (n0 + nstep * tt) * 128;
#pragma unroll
            for (int ii = 0; ii < 4; ++ii) {
#pragma unroll
                for (int j = 0; j < 4; ++j) {
                    int row = rowBase + MW + ii * 16 + g;
                    int col = colBase + NW + j * 8 + 2 * c;
                    epi<MODE>(args, row, col, acc[ii][j][0], acc[ii][j][1]);
                    epi<MODE>(args, row + 8, col, acc[ii][j][2], acc[ii][j][3]);
                }
            }
            if (i + 1 < total) {
#pragma unroll
                for (int ii = 0; ii < 4; ++ii)
#pragma unroll
                    for (int j = 0; j < 4; ++j)
#pragma unroll
                        for (int e = 0; e < 4; ++e) acc[ii][j][e] = 0.0f;
            }
        }
    }
}

struct RecArgs {
    const __half *N16, *P, *x0, *W1T, *WurT, *WkT;
    __half *HX16, *X0H16, *XTH16, *RH16, *U;
    const float *b_u, *b_r, *b_k;
    float* hx;
};

__global__ void __launch_bounds__(256, 2) recurrence_pk(RecArgs R) {
    extern __shared__ char sm[];
    uint32_t su = smem_u32(sm);
    int tid = threadIdx.x;
    int warp = tid >> 5, lane = tid & 31;
    int MW = (warp & 1) * 64, NW = (warp >> 1) * 32;
    int g = lane >> 2, c = lane & 3;
    int grp = blockIdx.x >> 2, mem = blockIdx.x & 3;
    int m_tile = grp;

    if (tid == 0) {
        MBARRIER_INIT(su + 0, 1);  MBARRIER_INIT(su + 8, 1);  MBARRIER_INIT(su + 16, 1);
        MBARRIER_INIT(su + 24, 8); MBARRIER_INIT(su + 32, 8); MBARRIER_INIT(su + 40, 8);
    }
    __syncthreads();

    uint32_t a_off = (uint32_t)((MW + (lane & 15)) * 144 + (lane >> 4) * 16);
    uint32_t b_off = (uint32_t)(PANEL_BYTES + (NW + (lane & 7) + ((lane >> 4) << 3)) * 144
                                + ((lane >> 3) & 1) * 16);

    Pipe P = {0, 0, 0, 1};   // producer parity 1: first empty-waits pass on fresh barriers

    for (int l = 0; l < Lsteps; ++l) {
        // ---- XI phase ----
        if (l == 0) {
            // hx0 == 0 -> elementwise; this CTA handles rows [m*128 + mem*32, +32)
#pragma unroll
            for (int it = 0; it < 8; ++it) {
                int e = (it * 256 + tid) * 8;
                int rl = e >> 9, col = e & 511;
                int row = m_tile * 128 + mem * 32 + rl;
                size_t pp2 = pidx(row, col);
                size_t idx = (size_t)row * Hdim + col;
                uint4 pv = *(const uint4*)(R.P + idx);
                uint4 xv = *(const uint4*)(R.x0 + pp2);
                uint4 lv = *(const uint4*)(R.N16 + pp2);
                const __half2* ph = (const __half2*)&pv;
                const __half2* xh = (const __half2*)&xv;
                const __half2* lh = (const __half2*)&lv;
                uint4 o0, o1;
                __half2* o0h = (__half2*)&o0;
                __half2* o1h = (__half2*)&o1;
#pragma unroll
                for (int q = 0; q < 4; ++q) {
                    float2 p = __half22float2(ph[q]);
                    float2 x = __half22float2(xh[q]);
                    float2 xl = __half22float2(lh[q]);
                    float s0 = sigmoidf_(p.x);
                    float s1 = sigmoidf_(p.y);
                    o0h[q] = __floats2half2_rn((1.f - s0) * x.x, (1.f - s1) * x.y);
                    o1h[q] = __floats2half2_rn(s0 * xl.x, s1 * xl.y);
                }
                *(uint4*)(R.X0H16 + pp2) = o0;
                *(uint4*)(R.XTH16 + pp2) = o1;
            }
        } else {
            GemmArgs a = {};
            a.A[0] = R.HX16;
            a.Bt = R.W1T; a.kpb = 8; a.kb0 = 0;
            a.P = R.P + (size_t)l * NH;
            a.x0 = R.x0; a.xl = R.N16 + (size_t)(l * 64) * 8 * PANEL_H;
            a.out16a = R.X0H16; a.out16b = R.XTH16;
            run_phase<MODE_XI>(a, 8, 1, mem, 0, m_tile, P, su, a_off, b_off,
                               lane, MW, NW, g, c);
        }
        group_barrier(grp, tid);

        // ---- UR phase: 2 tiles (n = mem and mem+4), continuous stream ----
        {
            GemmArgs a = {};
            a.Bt = R.WurT; a.kpb = 24;
            a.bias0 = R.b_u; a.bias1 = R.b_r; a.hxp = R.HX16;
            a.out16a = R.U; a.out16b = R.RH16;
            int kb;
            if (l == 0) {
                a.A[0] = R.X0H16; a.A[1] = R.XTH16; a.kb0 = 8; kb = 16;
            } else {
                a.A[0] = R.HX16; a.A[1] = R.X0H16; a.A[2] = R.XTH16; a.kb0 = 0; kb = 24;
            }
            run_phase<MODE_UR>(a, kb, 2, mem, 4, m_tile, P, su, a_off, b_off,
                               lane, MW, NW, g, c);
        }
        group_barrier(grp, tid);

        // ---- K phase ----
        {
            GemmArgs a = {};
            a.A[0] = R.X0H16; a.A[1] = R.XTH16; a.A[2] = R.RH16;
            a.Bt = R.WkT; a.kpb = 24; a.kb0 = 0;
            a.bias0 = R.b_k; a.U = R.U; a.hxp = R.HX16;
            a.out16a = R.HX16;
            a.out0 = (l == Lsteps - 1) ? R.hx : nullptr;
            run_phase<MODE_K>(a, l == 0 ? 16 : 24, 1, mem, 0, m_tile, P, su, a_off, b_off,
                              lane, MW, NW, g, c);
        }
        if (l < Lsteps - 1) group_barrier(grp, tid);
    }
}

// ---------------- weight transpose into panels -----------------------------------
struct TransJobs {
    const float* src[7];
    __half* dst[7];
    int kpb[7];
    int nbase[7];
    int kbase[7];
    int ktiles[7];
    int tileofs[7];
};

__global__ void transposeAll(TransJobs J) {
    __shared__ float t[32][33];
    int bid = blockIdx.x;
    int job = 0;
#pragma unroll
    for (int i = 1; i < 7; ++i)
        if (bid >= J.tileofs[i]) job = i;
    int local = bid - J.tileofs[job];
    int kt = J.ktiles[job];
    int kb = (local % kt) * 32;
    int nb = (local / kt) * 32;
    const float* src = J.src[job];
    __half* dst = J.dst[job];
    int KPB = J.kpb[job];
    int tx = threadIdx.x, ty = threadIdx.y;
#pragma unroll
    for (int i = 0; i < 32; i += 8)
        t[ty + i][tx] = src[(size_t)(kb + ty + i) * 512 + nb + tx];
    __syncthreads();
    int k = J.kbase[job] + kb + tx;
#pragma unroll
    for (int i = 0; i < 32; i += 8) {
        int n = J.nbase[job] + nb + ty + i;
        size_t off = ((size_t)((n >> 7) * KPB + (k >> 6))) * PANEL_H + (n & 127) * 72 + (k & 63);
        dst[off] = __float2half_rn(t[tx][ty + i]);
    }
}

// ---------------- fp32 -> fp16 convert into panels --------------------------------
__global__ void f2h_panel(const float* __restrict__ src, __half* __restrict__ dst, int n) {
    int i = (blockIdx.x * blockDim.x + threadIdx.x) * 8;
    if (i >= n) return;
    float4 v0 = *(const float4*)(src + i);
    float4 v1 = *(const float4*)(src + i + 4);
    __half2 h[4] = {__floats2half2_rn(v0.x, v0.y), __floats2half2_rn(v0.z, v0.w),
                    __floats2half2_rn(v1.x, v1.y), __floats2half2_rn(v1.z, v1.w)};
    int row = i >> 9, col = i & 511;
    size_t off = ((size_t)((row >> 7) * 8 + (col >> 6))) * PANEL_H + (row & 127) * 72 + (col & 63);
    *(uint4*)(dst + off) = *(uint4*)h;
}

// ---------------- step-0 XI elementwise (fallback path) ----------------------------
__global__ void xi0_kernel(const __half* __restrict__ P0,
                           const __half* __restrict__ x0p, const __half* __restrict__ xlp,
                           __half* __restrict__ X0H, __half* __restrict__ XTH) {
    int i = (blockIdx.x * blockDim.x + threadIdx.x) * 8;
    int row = i >> 9, col = i & 511;
    size_t pp = pidx(row, col);
    size_t idx = (size_t)row * Hdim + col;
    uint4 pv = *(const uint4*)(P0 + idx);
    uint4 xv = *(const uint4*)(x0p + pp);
    uint4 lv = *(const uint4*)(xlp + pp);
    const __half2* ph = (const __half2*)&pv;
    const __half2* xh = (const __half2*)&xv;
    const __half2* lh = (const __half2*)&lv;
    uint4 o0, o1;
    __half2* o0h = (__half2*)&o0;
    __half2* o1h = (__half2*)&o1;
#pragma unroll
    for (int q = 0; q < 4; ++q) {
        float2 p = __half22float2(ph[q]);
        float2 x = __half22float2(xh[q]);
        float2 l = __half22float2(lh[q]);
        float s0 = sigmoidf_(p.x);
        float s1 = sigmoidf_(p.y);
        o0h[q] = __floats2half2_rn((1.f - s0) * x.x, (1.f - s1) * x.y);
        o1h[q] = __floats2half2_rn(s0 * l.x, s1 * l.y);
    }
    *(uint4*)(X0H + pp) = o0;
    *(uint4*)(XTH + pp) = o1;
}

// ---------------- host --------------------------------------------------------------
template <int MODE>
static void run_gemm(const GemmArgs& a, int mTiles, int nTiles, int kblocks) {
    cudaFuncSetAttribute(gemm_bulk<MODE>, cudaFuncAttributeMaxDynamicSharedMemorySize,
                         SMEM_BYTES);
    dim3 grid(nTiles, mTiles);
    gemm_bulk<MODE><<<grid, 256, SMEM_BYTES>>>(a, kblocks);
}

extern "C" void kernel_launch(void* const* d_in, const int* in_sizes, int n_in,
                              void* d_out, int out_size) {
    const float* edge = (const float*)d_in[0];
    const float* node = (const float*)d_in[1];
    const float* W_xi = (const float*)d_in[2];
    const float* b_xi = (const float*)d_in[3];
    const float* W_u  = (const float*)d_in[4];
    const float* b_u  = (const float*)d_in[5];
    const float* W_r  = (const float*)d_in[6];
    const float* b_r  = (const float*)d_in[7];
    const float* W_k  = (const float*)d_in[8];
    const float* b_k  = (const float*)d_in[9];
    float* hx = (float*)d_out;

    __half *P, *C0, *U;
    __half *E16, *N16, *X0H16, *XTH16, *RH16, *HX16, *W1T, *WpT, *W3T, *WurT, *WkT;
    unsigned *grpCnt, *grpGen;
    cudaGetSymbolAddress((void**)&P,     g_P);
    cudaGetSymbolAddress((void**)&C0,    g_C0);
    cudaGetSymbolAddress((void**)&U,     g_U);
    cudaGetSymbolAddress((void**)&E16,   g_E16);
    cudaGetSymbolAddress((void**)&N16,   g_N16);
    cudaGetSymbolAddress((void**)&X0H16, g_X0H16);
    cudaGetSymbolAddress((void**)&XTH16, g_XTH16);
    cudaGetSymbolAddress((void**)&RH16,  g_RH16);
    cudaGetSymbolAddress((void**)&HX16,  g_HX16);
    cudaGetSymbolAddress((void**)&W1T,   g_W1T);
    cudaGetSymbolAddress((void**)&WpT,   g_WpT);
    cudaGetSymbolAddress((void**)&W3T,   g_W3T);
    cudaGetSymbolAddress((void**)&WurT,  g_WurT);
    cudaGetSymbolAddress((void**)&WkT,   g_WkT);
    cudaGetSymbolAddress((void**)&grpCnt, g_grpCnt);
    cudaGetSymbolAddress((void**)&grpGen, g_grpGen);

    cudaMemsetAsync(HX16, 0, sizeof(g_HX16), 0);
    cudaMemsetAsync(grpCnt, 0, sizeof(g_grpCnt), 0);
    cudaMemsetAsync(grpGen, 0, sizeof(g_grpGen), 0);

    // fp32 -> fp16 panels for edge / node (incl. x0)
    {
        int nE = Lsteps * NH;
        int nN = (Lsteps + 1) * NH;
        f2h_panel<<<(nE / 8 + 255) / 256, 256>>>(edge, E16, nE);
        f2h_panel<<<(nN / 8 + 255) / 256, 256>>>(node, N16, nN);
    }

    // weight transpose -> fp16 panels
    {
        TransJobs J;
        const float* srcs[7] = {W_xi, W_xi + 512 * 512, W_xi + 1536 * 512,
                                W_xi + 1024 * 512, W_u, W_r, W_k};
        __half* dsts[7] = {W1T, WpT, WpT, W3T, WurT, WurT, WkT};
        int kpbs[7]  = {8, 16, 16, 8, 24, 24, 24};
        int nbases[7] = {0, 0, 0, 0, 0, 512, 0};
        int kbases[7] = {0, 0, 512, 0, 0, 0, 0};
        int kts[7] = {16, 16, 16, 16, 48, 48, 48};
        int ofs = 0;
        for (int i = 0; i < 7; ++i) {
            J.src[i] = srcs[i]; J.dst[i] = dsts[i]; J.kpb[i] = kpbs[i];
            J.nbase[i] = nbases[i]; J.kbase[i] = kbases[i];
            J.ktiles[i] = kts[i]; J.tileofs[i] = ofs;
            ofs += kts[i] * 16;
        }
        transposeAll<<<ofs, dim3(32, 8)>>>(J);
    }

    const __half* x016 = N16 + (size_t)1024 * 8 * PANEL_H;

    // C0 = x0 @ W3 + b_xi (precedes PRE which folds it into P)
    {
        GemmArgs a = {};
        a.A[0] = x016;
        a.Bt = W3T; a.kpb = 8;
        a.bias0 = b_xi; a.out16a = C0;
        run_gemm<MODE_C0>(a, 64, 4, 8);
    }
    // PRE: P[l] = el @ W2 + xl @ W4 + C0
    {
        GemmArgs a = {};
        a.A[0] = E16; a.A[1] = N16;
        a.Bt = WpT; a.kpb = 16;
        a.C0 = C0;
        a.out16a = P;
        run_gemm<MODE_PRE>(a, 1024, 4, 16);
    }

    // persistent recurrence (64 groups x 4 CTAs) with launch-path fallback
    cudaFuncSetAttribute(recurrence_pk, cudaFuncAttributeMaxDynamicSharedMemorySize,
                         SMEM_BYTES);
    int dev = 0, smCount = 0, occ = 0;
    cudaGetDevice(&dev);
    cudaDeviceGetAttribute(&smCount, cudaDevAttrMultiProcessorCount, dev);
    cudaOccupancyMaxActiveBlocksPerMultiprocessor(&occ, recurrence_pk, 256, SMEM_BYTES);

    if (occ * smCount >= 256) {
        RecArgs R;
        R.N16 = N16; R.P = P; R.x0 = x016;
        R.W1T = W1T; R.WurT = WurT; R.WkT = WkT;
        R.HX16 = HX16; R.X0H16 = X0H16; R.XTH16 = XTH16; R.RH16 = RH16; R.U = U;
        R.b_u = b_u; R.b_r = b_r; R.b_k = b_k;
        R.hx = hx;
        recurrence_pk<<<256, 256, SMEM_BYTES>>>(R);
    } else {
        // fallback: R12 launch-based loop
        for (int l = 0; l < Lsteps; ++l) {
            if (l == 0) {
                xi0_kernel<<<NH / 8 / 256, 256>>>(P, x016, N16, X0H16, XTH16);
            } else {
                GemmArgs a = {};
                a.A[0] = HX16;
                a.Bt = W1T; a.kpb = 8;
                a.P = P + (size_t)l * NH;
                a.x0 = x016; a.xl = N16 + (size_t)(l * 64) * 8 * PANEL_H;
                a.out16a = X0H16; a.out16b = XTH16;
                run_gemm<MODE_XI>(a, 64, 4, 8);
            }
            {
                GemmArgs a = {};
                a.Bt = WurT; a.kpb = 24;
                a.bias0 = b_u; a.bias1 = b_r; a.hxp = HX16;
                a.out16a = U; a.out16b = RH16;
                if (l == 0) {
                    a.A[0] = X0H16; a.A[1] = XTH16; a.kb0 = 8;
                    run_gemm<MODE_UR>(a, 64, 8, 16);
                } else {
                    a.A[0] = HX16; a.A[1] = X0H16; a.A[2] = XTH16;
                    run_gemm<MODE_UR>(a, 64, 8, 24);
                }
            }
            {
                GemmArgs a = {};
                a.A[0] = X0H16; a.A[1] = XTH16; a.A[2] = RH16;
                a.Bt = WkT; a.kpb = 24;
                a.bias0 = b_k; a.U = U; a.hxp = HX16;
                a.out16a = HX16;
                a.out0 = (l == Lsteps - 1) ? hx : nullptr;
                run_gemm<MODE_K>(a, 64, 4, l == 0 ? 16 : 24);
            }
        }
    }
}